// round 4
// baseline (speedup 1.0000x reference)
#include <cuda_runtime.h>
#include <math.h>

#define N_NODES 50000
#define N_EDGES 800000
#define HDIM 128
#define CDIM 16

// ---------------- scratch (device globals; no allocation) ----------------
__device__ int   g_is64;
__device__ int   g_r32[N_EDGES];
__device__ int   g_c32[N_EDGES];
__device__ int   g_cnt[N_NODES];          // in-degree (excl. self loop)
__device__ int   g_cur[N_NODES];          // fill cursors
__device__ int   g_ptr[N_NODES + 1];      // CSR offsets by col
__device__ int   g_bsum[64];
__device__ int   g_bsumx[64];
__device__ float g_dinv[N_NODES];
__device__ int   g_src[N_EDGES];          // CSR: source node per edge
__device__ float g_wn[N_EDGES];           // CSR: dinv[row]*dinv[col]
__device__ float g_y[(size_t)N_NODES * HDIM];   // GEMM output
__device__ float g_h[(size_t)N_NODES * HDIM];   // activations

// ---------------- dtype detection: int64 vs int32 edge_index --------------
// int64 values in [0, 50000) -> every odd 32-bit word is 0.
__global__ void k_detect(const int* __restrict__ e) {
    __shared__ int any;
    if (threadIdx.x == 0) any = 0;
    __syncthreads();
    int v = e[2 * threadIdx.x + 1];
    if (v != 0) atomicOr(&any, 1);
    __syncthreads();
    if (threadIdx.x == 0) g_is64 = (any == 0) ? 1 : 0;
}

__global__ void k_convert(const void* __restrict__ edge) {
    int e = blockIdx.x * blockDim.x + threadIdx.x;
    if (e >= N_EDGES) return;
    if (g_is64) {
        const long long* p = (const long long*)edge;
        g_r32[e] = (int)p[e];
        g_c32[e] = (int)p[N_EDGES + e];
    } else {
        const int* p = (const int*)edge;
        g_r32[e] = p[e];
        g_c32[e] = p[N_EDGES + e];
    }
}

__global__ void k_init() {
    int i = blockIdx.x * blockDim.x + threadIdx.x;
    if (i < N_NODES) { g_cnt[i] = 0; g_cur[i] = 0; }
}

__global__ void k_hist() {
    int e = blockIdx.x * blockDim.x + threadIdx.x;
    if (e < N_EDGES) atomicAdd(&g_cnt[g_c32[e]], 1);
}

__global__ void k_dinv() {
    int i = blockIdx.x * blockDim.x + threadIdx.x;
    if (i < N_NODES) g_dinv[i] = rsqrtf((float)(g_cnt[i] + 1));
}

// 3-kernel exclusive scan of g_cnt -> g_ptr
__global__ void k_scan1() {
    __shared__ int s[1024];
    int idx = blockIdx.x * 1024 + threadIdx.x;
    int v = (idx < N_NODES) ? g_cnt[idx] : 0;
    s[threadIdx.x] = v;
    __syncthreads();
    for (int off = 1; off < 1024; off <<= 1) {
        int t = (threadIdx.x >= off) ? s[threadIdx.x - off] : 0;
        __syncthreads();
        s[threadIdx.x] += t;
        __syncthreads();
    }
    if (idx < N_NODES) g_ptr[idx] = s[threadIdx.x] - v;   // exclusive, block-local
    if (threadIdx.x == 1023) g_bsum[blockIdx.x] = s[1023];
}

__global__ void k_scan2(int nblocks) {
    if (threadIdx.x == 0 && blockIdx.x == 0) {
        int acc = 0;
        for (int i = 0; i < nblocks; i++) { g_bsumx[i] = acc; acc += g_bsum[i]; }
    }
}

__global__ void k_scan3() {
    int idx = blockIdx.x * 1024 + threadIdx.x;
    if (idx < N_NODES) g_ptr[idx] += g_bsumx[blockIdx.x];
    if (idx == 0) g_ptr[N_NODES] = N_EDGES;
}

__global__ void k_fill() {
    int e = blockIdx.x * blockDim.x + threadIdx.x;
    if (e >= N_EDGES) return;
    int c = g_c32[e];
    int r = g_r32[e];
    int pos = atomicAdd(&g_cur[c], 1);
    int idx = g_ptr[c] + pos;
    g_src[idx] = r;
    g_wn[idx] = g_dinv[r] * g_dinv[c];
}

// ---------------- GEMM: Y[n,128] = (A .* scale?) @ W[128,128] -------------
// Static smem only (no cudaFuncSetAttribute): W is k-tiled 16x128 (8KB),
// A tile 64x17 padded. 256 threads; 4x8 register tile per thread.
__global__ void k_gemm(const float* __restrict__ A, const float* __restrict__ scale,
                       const float* __restrict__ W, float* __restrict__ Y) {
    __shared__ float Ws[16 * 128];   // current k-tile of W
    __shared__ float As[64 * 17];    // 64-row A tile, padded
    int tid = threadIdx.x;
    int row0 = blockIdx.x * 64;

    int ty = tid >> 4, tx = tid & 15;
    int r0 = ty * 4, c0 = tx * 8;
    float acc[4][8];
#pragma unroll
    for (int i = 0; i < 4; i++)
#pragma unroll
        for (int j = 0; j < 8; j++) acc[i][j] = 0.f;

    int lr = tid >> 2;           // 0..63
    int lc = (tid & 3) * 4;      // 0,4,8,12

    for (int k0 = 0; k0 < 128; k0 += 16) {
        float4 av = make_float4(0.f, 0.f, 0.f, 0.f);
        int gr = row0 + lr;
        if (gr < N_NODES)
            av = *(const float4*)(A + (size_t)gr * HDIM + k0 + lc);
        if (scale) {
            av.x *= scale[k0 + lc];
            av.y *= scale[k0 + lc + 1];
            av.z *= scale[k0 + lc + 2];
            av.w *= scale[k0 + lc + 3];
        }
        __syncthreads();   // previous iteration's compute done
        As[lr * 17 + lc]     = av.x;
        As[lr * 17 + lc + 1] = av.y;
        As[lr * 17 + lc + 2] = av.z;
        As[lr * 17 + lc + 3] = av.w;
        // load W k-tile: rows k0..k0+15, 2048 floats = 512 float4
#pragma unroll
        for (int i = tid; i < 512; i += 256)
            ((float4*)Ws)[i] = ((const float4*)(W + k0 * 128))[i];
        __syncthreads();
#pragma unroll
        for (int kk = 0; kk < 16; kk++) {
            float a0 = As[(r0 + 0) * 17 + kk];
            float a1 = As[(r0 + 1) * 17 + kk];
            float a2 = As[(r0 + 2) * 17 + kk];
            float a3 = As[(r0 + 3) * 17 + kk];
            const float4 b0 = *(const float4*)(Ws + kk * 128 + c0);
            const float4 b1 = *(const float4*)(Ws + kk * 128 + c0 + 4);
            acc[0][0] += a0 * b0.x; acc[0][1] += a0 * b0.y; acc[0][2] += a0 * b0.z; acc[0][3] += a0 * b0.w;
            acc[0][4] += a0 * b1.x; acc[0][5] += a0 * b1.y; acc[0][6] += a0 * b1.z; acc[0][7] += a0 * b1.w;
            acc[1][0] += a1 * b0.x; acc[1][1] += a1 * b0.y; acc[1][2] += a1 * b0.z; acc[1][3] += a1 * b0.w;
            acc[1][4] += a1 * b1.x; acc[1][5] += a1 * b1.y; acc[1][6] += a1 * b1.z; acc[1][7] += a1 * b1.w;
            acc[2][0] += a2 * b0.x; acc[2][1] += a2 * b0.y; acc[2][2] += a2 * b0.z; acc[2][3] += a2 * b0.w;
            acc[2][4] += a2 * b1.x; acc[2][5] += a2 * b1.y; acc[2][6] += a2 * b1.z; acc[2][7] += a2 * b1.w;
            acc[3][0] += a3 * b0.x; acc[3][1] += a3 * b0.y; acc[3][2] += a3 * b0.z; acc[3][3] += a3 * b0.w;
            acc[3][4] += a3 * b1.x; acc[3][5] += a3 * b1.y; acc[3][6] += a3 * b1.z; acc[3][7] += a3 * b1.w;
        }
    }

#pragma unroll
    for (int i = 0; i < 4; i++) {
        int gr = row0 + r0 + i;
        if (gr < N_NODES) {
            float4 o0 = make_float4(acc[i][0], acc[i][1], acc[i][2], acc[i][3]);
            float4 o1 = make_float4(acc[i][4], acc[i][5], acc[i][6], acc[i][7]);
            *(float4*)(Y + (size_t)gr * HDIM + c0)     = o0;
            *(float4*)(Y + (size_t)gr * HDIM + c0 + 4) = o1;
        }
    }
}

// ---------------- aggregation: h[c] = gelu(sum_e wn*y[src] + dinv^2*y[c] + b)
__device__ __forceinline__ float gelu_exact(float v) {
    return 0.5f * v * (1.f + erff(v * 0.70710678118654752f));
}

__global__ void k_agg(const float* __restrict__ Y, const float* __restrict__ b,
                      float* __restrict__ H) {
    int gw = (blockIdx.x * blockDim.x + threadIdx.x) >> 5;   // node id (warp/node)
    if (gw >= N_NODES) return;
    int lane = threadIdx.x & 31;
    int c = gw;
    float dc = g_dinv[c];
    float sw = dc * dc;                       // self-loop weight
    const float4 self = *(const float4*)(Y + (size_t)c * HDIM + lane * 4);
    float4 acc = make_float4(sw * self.x, sw * self.y, sw * self.z, sw * self.w);

    int beg = g_ptr[c], end = g_ptr[c + 1];
    for (int base = beg; base < end; base += 32) {
        int i = base + lane;
        int s = (i < end) ? g_src[i] : 0;
        float w = (i < end) ? g_wn[i] : 0.f;
        int m = min(32, end - base);
        for (int j = 0; j < m; j++) {
            int   sj = __shfl_sync(0xffffffffu, s, j);
            float wj = __shfl_sync(0xffffffffu, w, j);
            const float4 v = *(const float4*)(Y + (size_t)sj * HDIM + lane * 4);
            acc.x += wj * v.x; acc.y += wj * v.y;
            acc.z += wj * v.z; acc.w += wj * v.w;
        }
    }
    const float4 bb = *(const float4*)(b + lane * 4);
    acc.x = gelu_exact(acc.x + bb.x);
    acc.y = gelu_exact(acc.y + bb.y);
    acc.z = gelu_exact(acc.z + bb.z);
    acc.w = gelu_exact(acc.w + bb.w);
    *(float4*)(H + (size_t)c * HDIM + lane * 4) = acc;
}

// ---------------- final: out = gelu(Y + lb1) @ lw2 + lb2 ------------------
__global__ void k_final(const float* __restrict__ Y, const float* __restrict__ lb1,
                        const float* __restrict__ lw2, const float* __restrict__ lb2,
                        float* __restrict__ out) {
    __shared__ float t[16 * 128];
    __shared__ float w2[128 * 16];
    __shared__ float sb1[128];
    __shared__ float sb2[16];
    int tid = threadIdx.x;
    int n0 = blockIdx.x * 16;

    for (int i = tid; i < 2048; i += 256) w2[i] = lw2[i];
    if (tid < 128) sb1[tid] = lb1[tid];
    if (tid < 16)  sb2[tid] = lb2[tid];
    __syncthreads();

    for (int i = tid; i < 2048; i += 256) {
        int n = i >> 7, f = i & 127;
        float v = Y[(size_t)(n0 + n) * HDIM + f] + sb1[f];
        t[i] = gelu_exact(v);
    }
    __syncthreads();

    int n = tid >> 4, c = tid & 15;
    float acc = sb2[c];
#pragma unroll 8
    for (int f = 0; f < 128; f++)
        acc += t[n * 128 + f] * w2[f * 16 + c];
    out[(size_t)(n0 + n) * CDIM + c] = acc;
}

// ---------------- launch ---------------------------------------------------
extern "C" void kernel_launch(void* const* d_in, const int* in_sizes, int n_in,
                              void* d_out, int out_size) {
    const float* x    = (const float*)d_in[0];
    const void*  edge = d_in[1];
    const float* imp  = (const float*)d_in[2];
    const float* W1   = (const float*)d_in[3];
    const float* b1   = (const float*)d_in[4];
    const float* W2   = (const float*)d_in[5];
    const float* b2   = (const float*)d_in[6];
    const float* W3   = (const float*)d_in[7];
    const float* b3   = (const float*)d_in[8];
    const float* lw1  = (const float*)d_in[9];
    const float* lb1  = (const float*)d_in[10];
    const float* lw2  = (const float*)d_in[11];
    const float* lb2  = (const float*)d_in[12];
    float* out = (float*)d_out;

    const int EB = (N_EDGES + 255) / 256;      // 3125
    const int NB = (N_NODES + 255) / 256;      // 196
    const int SB = (N_NODES + 1023) / 1024;    // 49
    const int GB = (N_NODES + 63) / 64;        // 782
    const int AB = (N_NODES + 3) / 4;          // 12500 (4 warps/block)
    const int FB = N_NODES / 16;               // 3125

    // device pointers to scratch
    float* y; cudaGetSymbolAddress((void**)&y, g_y);
    float* h; cudaGetSymbolAddress((void**)&h, g_h);

    // --- CSR build (once per launch; reused for all 3 conv layers) ---
    k_detect<<<1, 256>>>((const int*)edge);
    k_convert<<<EB, 256>>>(edge);
    k_init<<<NB, 256>>>();
    k_hist<<<EB, 256>>>();
    k_dinv<<<NB, 256>>>();
    k_scan1<<<SB, 1024>>>();
    k_scan2<<<1, 32>>>(SB);
    k_scan3<<<SB, 1024>>>();
    k_fill<<<EB, 256>>>();

    // --- layer 1: (x*importance) @ W1 -> propagate + b1 + gelu ---
    k_gemm<<<GB, 256>>>(x, imp, W1, y);
    k_agg<<<AB, 128>>>(y, b1, h);
    // --- layer 2 ---
    k_gemm<<<GB, 256>>>(h, nullptr, W2, y);
    k_agg<<<AB, 128>>>(y, b2, h);
    // --- layer 3 ---
    k_gemm<<<GB, 256>>>(h, nullptr, W3, y);
    k_agg<<<AB, 128>>>(y, b3, h);
    // --- head: gelu(h@lw1+lb1) @ lw2 + lb2 ---
    k_gemm<<<GB, 256>>>(h, nullptr, lw1, y);
    k_final<<<FB, 256>>>(y, lb1, lw2, lb2, out);
}

// round 5
// speedup vs baseline: 1.2642x; 1.2642x over previous
#include <cuda_runtime.h>
#include <math.h>

#define N_NODES 50000
#define N_EDGES 800000
#define HDIM 128
#define CDIM 16

// ---------------- scratch (device globals; no allocation) ----------------
__device__ int   g_is64;
__device__ int   g_r32[N_EDGES];
__device__ int   g_c32[N_EDGES];
__device__ int   g_cnt[N_NODES];          // in-degree (excl. self loop)
__device__ int   g_cur[N_NODES];          // fill cursors
__device__ int   g_ptr[N_NODES + 1];      // CSR offsets by col
__device__ int   g_bsum[64];
__device__ int   g_bsumx[64];
__device__ float g_dinv[N_NODES];
__device__ int   g_src[N_EDGES];          // CSR: source node per edge
__device__ float g_wn[N_EDGES];           // CSR: dinv[row]*dinv[col]
__device__ float g_y[(size_t)N_NODES * HDIM];   // GEMM output
__device__ float g_h[(size_t)N_NODES * HDIM];   // activations

// ---------------- dtype detection: int64 vs int32 edge_index --------------
__global__ void k_detect(const int* __restrict__ e) {
    __shared__ int any;
    if (threadIdx.x == 0) any = 0;
    __syncthreads();
    int v = e[2 * threadIdx.x + 1];
    if (v != 0) atomicOr(&any, 1);
    __syncthreads();
    if (threadIdx.x == 0) g_is64 = (any == 0) ? 1 : 0;
}

__global__ void k_init() {
    int i = blockIdx.x * blockDim.x + threadIdx.x;
    if (i < N_NODES) { g_cnt[i] = 0; g_cur[i] = 0; }
}

// fused convert + histogram (one pass over edges)
__global__ void k_convert_hist(const void* __restrict__ edge) {
    int e = blockIdx.x * blockDim.x + threadIdx.x;
    if (e >= N_EDGES) return;
    int r, c;
    if (g_is64) {
        const long long* p = (const long long*)edge;
        r = (int)p[e];
        c = (int)p[N_EDGES + e];
    } else {
        const int* p = (const int*)edge;
        r = p[e];
        c = p[N_EDGES + e];
    }
    g_r32[e] = r;
    g_c32[e] = c;
    atomicAdd(&g_cnt[c], 1);
}

__global__ void k_dinv() {
    int i = blockIdx.x * blockDim.x + threadIdx.x;
    if (i < N_NODES) g_dinv[i] = rsqrtf((float)(g_cnt[i] + 1));
}

// 3-kernel exclusive scan of g_cnt -> g_ptr
__global__ void k_scan1() {
    __shared__ int s[1024];
    int idx = blockIdx.x * 1024 + threadIdx.x;
    int v = (idx < N_NODES) ? g_cnt[idx] : 0;
    s[threadIdx.x] = v;
    __syncthreads();
    for (int off = 1; off < 1024; off <<= 1) {
        int t = (threadIdx.x >= off) ? s[threadIdx.x - off] : 0;
        __syncthreads();
        s[threadIdx.x] += t;
        __syncthreads();
    }
    if (idx < N_NODES) g_ptr[idx] = s[threadIdx.x] - v;
    if (threadIdx.x == 1023) g_bsum[blockIdx.x] = s[1023];
}

__global__ void k_scan2(int nblocks) {
    if (threadIdx.x == 0 && blockIdx.x == 0) {
        int acc = 0;
        for (int i = 0; i < nblocks; i++) { g_bsumx[i] = acc; acc += g_bsum[i]; }
    }
}

__global__ void k_scan3() {
    int idx = blockIdx.x * 1024 + threadIdx.x;
    if (idx < N_NODES) g_ptr[idx] += g_bsumx[blockIdx.x];
    if (idx == 0) g_ptr[N_NODES] = N_EDGES;
}

__global__ void k_fill() {
    int e = blockIdx.x * blockDim.x + threadIdx.x;
    if (e >= N_EDGES) return;
    int c = g_c32[e];
    int r = g_r32[e];
    int pos = atomicAdd(&g_cur[c], 1);
    int idx = g_ptr[c] + pos;
    g_src[idx] = r;
    g_wn[idx] = g_dinv[r] * g_dinv[c];
}

// ---------------- tensor-core GEMM (3xTF32): Y = (A .* scale?) @ W ----------
// mma.sync.m16n8k8 tf32, split-precision: x = big(tf32) + small(tf32).
// D += Ab*Bb + Ab*Bs + As*Bb  -> ~fp32 accuracy on the tensor pipe.
// 256 threads = 8 warps as 2(M)x4(N); each warp: M64 x N32.
// K tiled by 16; all smem static (34.3 KB).

__device__ __forceinline__ unsigned f2tf(float x) {
    unsigned r;
    asm("cvt.rna.tf32.f32 %0, %1;" : "=r"(r) : "f"(x));
    return r;
}

__device__ __forceinline__ void mma_tf32(float* d, const unsigned* a, const unsigned* b) {
    asm volatile(
        "mma.sync.aligned.m16n8k8.row.col.f32.tf32.tf32.f32 "
        "{%0,%1,%2,%3}, {%4,%5,%6,%7}, {%8,%9}, {%0,%1,%2,%3};"
        : "+f"(d[0]), "+f"(d[1]), "+f"(d[2]), "+f"(d[3])
        : "r"(a[0]), "r"(a[1]), "r"(a[2]), "r"(a[3]), "r"(b[0]), "r"(b[1]));
}

#define AS_STRIDE 17
#define WS_STRIDE 132

__global__ void k_gemm_tc(const float* __restrict__ A, const float* __restrict__ scale,
                          const float* __restrict__ W, float* __restrict__ Y) {
    __shared__ float Ab[128 * AS_STRIDE];
    __shared__ float Al[128 * AS_STRIDE];
    __shared__ float Wb[16 * WS_STRIDE];
    __shared__ float Wl[16 * WS_STRIDE];

    int tid  = threadIdx.x;
    int lane = tid & 31;
    int wid  = tid >> 5;
    int wm   = wid >> 2;          // 0..1  (M split)
    int wn   = wid & 3;           // 0..3  (N split)
    int g    = lane >> 2;         // 0..7
    int t    = lane & 3;          // 0..3
    int row0 = blockIdx.x * 128;

    float acc[4][4][4];           // [mt][nt][reg]
#pragma unroll
    for (int mt = 0; mt < 4; mt++)
#pragma unroll
        for (int nt = 0; nt < 4; nt++)
#pragma unroll
            for (int r = 0; r < 4; r++) acc[mt][nt][r] = 0.f;

    for (int kt = 0; kt < 8; kt++) {
        // ---- stage A tile: 128 rows x 16 k (split big/small) ----
#pragma unroll
        for (int ii = 0; ii < 2; ii++) {
            int i  = tid + ii * 256;          // float4 index 0..511
            int r  = i >> 2;                  // 0..127
            int kq = (i & 3) * 4;             // 0,4,8,12
            float4 v = make_float4(0.f, 0.f, 0.f, 0.f);
            int gr = row0 + r;
            if (gr < N_NODES)
                v = *(const float4*)(A + (size_t)gr * HDIM + kt * 16 + kq);
            if (scale) {
                v.x *= scale[kt * 16 + kq];
                v.y *= scale[kt * 16 + kq + 1];
                v.z *= scale[kt * 16 + kq + 2];
                v.w *= scale[kt * 16 + kq + 3];
            }
            float* pb = Ab + r * AS_STRIDE + kq;
            float* pl = Al + r * AS_STRIDE + kq;
            unsigned bx = f2tf(v.x); pb[0] = __uint_as_float(bx); pl[0] = __uint_as_float(f2tf(v.x - __uint_as_float(bx)));
            unsigned by = f2tf(v.y); pb[1] = __uint_as_float(by); pl[1] = __uint_as_float(f2tf(v.y - __uint_as_float(by)));
            unsigned bz = f2tf(v.z); pb[2] = __uint_as_float(bz); pl[2] = __uint_as_float(f2tf(v.z - __uint_as_float(bz)));
            unsigned bw = f2tf(v.w); pb[3] = __uint_as_float(bw); pl[3] = __uint_as_float(f2tf(v.w - __uint_as_float(bw)));
        }
        // ---- stage W tile: 16 k-rows x 128 n (split big/small) ----
#pragma unroll
        for (int ii = 0; ii < 2; ii++) {
            int i  = tid + ii * 256;          // float4 index 0..511
            int kr = i >> 5;                  // 0..15
            int nq = (i & 31) * 4;            // 0..124
            float4 v = *(const float4*)(W + (size_t)(kt * 16 + kr) * HDIM + nq);
            float* pb = Wb + kr * WS_STRIDE + nq;
            float* pl = Wl + kr * WS_STRIDE + nq;
            unsigned bx = f2tf(v.x); pb[0] = __uint_as_float(bx); pl[0] = __uint_as_float(f2tf(v.x - __uint_as_float(bx)));
            unsigned by = f2tf(v.y); pb[1] = __uint_as_float(by); pl[1] = __uint_as_float(f2tf(v.y - __uint_as_float(by)));
            unsigned bz = f2tf(v.z); pb[2] = __uint_as_float(bz); pl[2] = __uint_as_float(f2tf(v.z - __uint_as_float(bz)));
            unsigned bw = f2tf(v.w); pb[3] = __uint_as_float(bw); pl[3] = __uint_as_float(f2tf(v.w - __uint_as_float(bw)));
        }
        __syncthreads();

#pragma unroll
        for (int ks = 0; ks < 2; ks++) {
            int k0 = ks * 8;
            unsigned afb[4][4], afl[4][4];
#pragma unroll
            for (int mt = 0; mt < 4; mt++) {
                int rb = wm * 64 + mt * 16;
                afb[mt][0] = __float_as_uint(Ab[(rb + g) * AS_STRIDE + k0 + t]);
                afb[mt][1] = __float_as_uint(Ab[(rb + g + 8) * AS_STRIDE + k0 + t]);
                afb[mt][2] = __float_as_uint(Ab[(rb + g) * AS_STRIDE + k0 + t + 4]);
                afb[mt][3] = __float_as_uint(Ab[(rb + g + 8) * AS_STRIDE + k0 + t + 4]);
                afl[mt][0] = __float_as_uint(Al[(rb + g) * AS_STRIDE + k0 + t]);
                afl[mt][1] = __float_as_uint(Al[(rb + g + 8) * AS_STRIDE + k0 + t]);
                afl[mt][2] = __float_as_uint(Al[(rb + g) * AS_STRIDE + k0 + t + 4]);
                afl[mt][3] = __float_as_uint(Al[(rb + g + 8) * AS_STRIDE + k0 + t + 4]);
            }
            unsigned bfb[4][2], bfl[4][2];
#pragma unroll
            for (int nt = 0; nt < 4; nt++) {
                int n0 = wn * 32 + nt * 8;
                bfb[nt][0] = __float_as_uint(Wb[(k0 + t) * WS_STRIDE + n0 + g]);
                bfb[nt][1] = __float_as_uint(Wb[(k0 + t + 4) * WS_STRIDE + n0 + g]);
                bfl[nt][0] = __float_as_uint(Wl[(k0 + t) * WS_STRIDE + n0 + g]);
                bfl[nt][1] = __float_as_uint(Wl[(k0 + t + 4) * WS_STRIDE + n0 + g]);
            }
#pragma unroll
            for (int mt = 0; mt < 4; mt++)
#pragma unroll
                for (int nt = 0; nt < 4; nt++) {
                    mma_tf32(acc[mt][nt], afb[mt], bfb[nt]);   // big*big
                    mma_tf32(acc[mt][nt], afb[mt], bfl[nt]);   // big*small
                    mma_tf32(acc[mt][nt], afl[mt], bfb[nt]);   // small*big
                }
        }
        __syncthreads();
    }

    // ---- epilogue ----
#pragma unroll
    for (int mt = 0; mt < 4; mt++) {
        int r1 = row0 + wm * 64 + mt * 16 + g;
        int r2 = r1 + 8;
#pragma unroll
        for (int nt = 0; nt < 4; nt++) {
            int c = wn * 32 + nt * 8 + 2 * t;
            if (r1 < N_NODES) {
                Y[(size_t)r1 * HDIM + c]     = acc[mt][nt][0];
                Y[(size_t)r1 * HDIM + c + 1] = acc[mt][nt][1];
            }
            if (r2 < N_NODES) {
                Y[(size_t)r2 * HDIM + c]     = acc[mt][nt][2];
                Y[(size_t)r2 * HDIM + c + 1] = acc[mt][nt][3];
            }
        }
    }
}

// ---------------- aggregation: h[c] = gelu(sum_e wn*y[src] + dinv^2*y[c] + b)
__device__ __forceinline__ float gelu_exact(float v) {
    return 0.5f * v * (1.f + erff(v * 0.70710678118654752f));
}

__global__ void k_agg(const float* __restrict__ Y, const float* __restrict__ b,
                      float* __restrict__ H) {
    int gw = (blockIdx.x * blockDim.x + threadIdx.x) >> 5;   // node id (warp/node)
    if (gw >= N_NODES) return;
    int lane = threadIdx.x & 31;
    int c = gw;
    float dc = g_dinv[c];
    float sw = dc * dc;                       // self-loop weight
    const float4 self = *(const float4*)(Y + (size_t)c * HDIM + lane * 4);
    float4 acc = make_float4(sw * self.x, sw * self.y, sw * self.z, sw * self.w);

    int beg = g_ptr[c], end = g_ptr[c + 1];
    for (int base = beg; base < end; base += 32) {
        int i = base + lane;
        int s = (i < end) ? g_src[i] : 0;
        float w = (i < end) ? g_wn[i] : 0.f;
        int m = min(32, end - base);
        for (int j = 0; j < m; j++) {
            int   sj = __shfl_sync(0xffffffffu, s, j);
            float wj = __shfl_sync(0xffffffffu, w, j);
            const float4 v = *(const float4*)(Y + (size_t)sj * HDIM + lane * 4);
            acc.x += wj * v.x; acc.y += wj * v.y;
            acc.z += wj * v.z; acc.w += wj * v.w;
        }
    }
    const float4 bb = *(const float4*)(b + lane * 4);
    acc.x = gelu_exact(acc.x + bb.x);
    acc.y = gelu_exact(acc.y + bb.y);
    acc.z = gelu_exact(acc.z + bb.z);
    acc.w = gelu_exact(acc.w + bb.w);
    *(float4*)(H + (size_t)c * HDIM + lane * 4) = acc;
}

// ---------------- final: out = gelu(Y + lb1) @ lw2 + lb2 ------------------
__global__ void k_final(const float* __restrict__ Y, const float* __restrict__ lb1,
                        const float* __restrict__ lw2, const float* __restrict__ lb2,
                        float* __restrict__ out) {
    __shared__ float t[16 * 128];
    __shared__ float w2[128 * 16];
    __shared__ float sb1[128];
    __shared__ float sb2[16];
    int tid = threadIdx.x;
    int n0 = blockIdx.x * 16;

    for (int i = tid; i < 2048; i += 256) w2[i] = lw2[i];
    if (tid < 128) sb1[tid] = lb1[tid];
    if (tid < 16)  sb2[tid] = lb2[tid];
    __syncthreads();

    for (int i = tid; i < 2048; i += 256) {
        int n = i >> 7, f = i & 127;
        float v = Y[(size_t)(n0 + n) * HDIM + f] + sb1[f];
        t[i] = gelu_exact(v);
    }
    __syncthreads();

    int n = tid >> 4, c = tid & 15;
    float acc = sb2[c];
#pragma unroll 8
    for (int f = 0; f < 128; f++)
        acc += t[n * 128 + f] * w2[f * 16 + c];
    out[(size_t)(n0 + n) * CDIM + c] = acc;
}

// ---------------- launch ---------------------------------------------------
extern "C" void kernel_launch(void* const* d_in, const int* in_sizes, int n_in,
                              void* d_out, int out_size) {
    const float* x    = (const float*)d_in[0];
    const void*  edge = d_in[1];
    const float* imp  = (const float*)d_in[2];
    const float* W1   = (const float*)d_in[3];
    const float* b1   = (const float*)d_in[4];
    const float* W2   = (const float*)d_in[5];
    const float* b2   = (const float*)d_in[6];
    const float* W3   = (const float*)d_in[7];
    const float* b3   = (const float*)d_in[8];
    const float* lw1  = (const float*)d_in[9];
    const float* lb1  = (const float*)d_in[10];
    const float* lw2  = (const float*)d_in[11];
    const float* lb2  = (const float*)d_in[12];
    float* out = (float*)d_out;

    const int EB = (N_EDGES + 255) / 256;      // 3125
    const int NB = (N_NODES + 255) / 256;      // 196
    const int SB = (N_NODES + 1023) / 1024;    // 49
    const int GB = (N_NODES + 127) / 128;      // 391 (tc gemm: 128 rows/block)
    const int AB = (N_NODES + 3) / 4;          // 12500 (4 warps/block)
    const int FB = N_NODES / 16;               // 3125

    float* y; cudaGetSymbolAddress((void**)&y, g_y);
    float* h; cudaGetSymbolAddress((void**)&h, g_h);

    // --- CSR build (once per launch; reused for all 3 conv layers) ---
    k_detect<<<1, 256>>>((const int*)edge);
    k_init<<<NB, 256>>>();
    k_convert_hist<<<EB, 256>>>(edge);
    k_dinv<<<NB, 256>>>();
    k_scan1<<<SB, 1024>>>();
    k_scan2<<<1, 32>>>(SB);
    k_scan3<<<SB, 1024>>>();
    k_fill<<<EB, 256>>>();

    // --- layer 1: (x*importance) @ W1 -> propagate + b1 + gelu ---
    k_gemm_tc<<<GB, 256>>>(x, imp, W1, y);
    k_agg<<<AB, 128>>>(y, b1, h);
    // --- layer 2 ---
    k_gemm_tc<<<GB, 256>>>(h, nullptr, W2, y);
    k_agg<<<AB, 128>>>(y, b2, h);
    // --- layer 3 ---
    k_gemm_tc<<<GB, 256>>>(h, nullptr, W3, y);
    k_agg<<<AB, 128>>>(y, b3, h);
    // --- head: gelu(h@lw1+lb1) @ lw2 + lb2 ---
    k_gemm_tc<<<GB, 256>>>(h, nullptr, lw1, y);
    k_final<<<FB, 256>>>(y, lb1, lw2, lb2, out);
}

// round 6
// speedup vs baseline: 1.4080x; 1.1138x over previous
#include <cuda_runtime.h>
#include <cuda_fp16.h>
#include <math.h>

#define N_NODES 50000
#define N_EDGES 800000
#define HDIM 128
#define CDIM 16

// ---------------- scratch (device globals; no allocation) ----------------
__device__ int   g_is64;
__device__ int   g_r32[N_EDGES];
__device__ int   g_c32[N_EDGES];
__device__ int   g_cnt[N_NODES];          // in-degree (excl. self loop)
__device__ int   g_cur[N_NODES];          // fill cursors
__device__ int   g_ptr[N_NODES + 1];      // CSR offsets by col
__device__ int   g_bsum[64];
__device__ float g_dinv[N_NODES];
__device__ int   g_src[N_EDGES];          // CSR: source node per edge
__device__ float g_wn[N_EDGES];           // CSR: dinv[row]*dinv[col]
__device__ __half2 g_y[(size_t)N_NODES * 64];   // GEMM output (fp16 messages)
__device__ float   g_h[(size_t)N_NODES * HDIM]; // activations (fp32)

// ---------------- detect dtype + zero counters (fused) --------------------
__global__ void k_detect_init(const int* __restrict__ e) {
    int i = blockIdx.x * blockDim.x + threadIdx.x;
    if (i < N_NODES) { g_cnt[i] = 0; g_cur[i] = 0; }
    if (blockIdx.x == 0) {
        __shared__ int any;
        if (threadIdx.x == 0) any = 0;
        __syncthreads();
        int v = e[2 * threadIdx.x + 1];   // odd words zero <=> int64 indices
        if (v != 0) atomicOr(&any, 1);
        __syncthreads();
        if (threadIdx.x == 0) g_is64 = (any == 0) ? 1 : 0;
    }
}

// fused convert + histogram (one pass over edges)
__global__ void k_convert_hist(const void* __restrict__ edge) {
    int e = blockIdx.x * blockDim.x + threadIdx.x;
    if (e >= N_EDGES) return;
    int r, c;
    if (g_is64) {
        const long long* p = (const long long*)edge;
        r = (int)p[e];
        c = (int)p[N_EDGES + e];
    } else {
        const int* p = (const int*)edge;
        r = p[e];
        c = p[N_EDGES + e];
    }
    g_r32[e] = r;
    g_c32[e] = c;
    atomicAdd(&g_cnt[c], 1);
}

// block-local exclusive scan of g_cnt -> g_ptr (+ dinv fused: has cnt in reg)
__global__ void k_scan1() {
    __shared__ int s[1024];
    int idx = blockIdx.x * 1024 + threadIdx.x;
    int v = (idx < N_NODES) ? g_cnt[idx] : 0;
    if (idx < N_NODES) g_dinv[idx] = rsqrtf((float)(v + 1));
    s[threadIdx.x] = v;
    __syncthreads();
    for (int off = 1; off < 1024; off <<= 1) {
        int t = (threadIdx.x >= off) ? s[threadIdx.x - off] : 0;
        __syncthreads();
        s[threadIdx.x] += t;
        __syncthreads();
    }
    if (idx < N_NODES) g_ptr[idx] = s[threadIdx.x] - v;
    if (threadIdx.x == 1023) g_bsum[blockIdx.x] = s[1023];
}

// add cross-block prefix (each block reduces its own prefix of g_bsum)
__global__ void k_scan3() {
    __shared__ int pre;
    if (threadIdx.x < 32) {
        int p = 0;
        for (int i = threadIdx.x; i < blockIdx.x; i += 32) p += g_bsum[i];
#pragma unroll
        for (int o = 16; o; o >>= 1) p += __shfl_xor_sync(0xffffffffu, p, o);
        if (threadIdx.x == 0) pre = p;
    }
    __syncthreads();
    int idx = blockIdx.x * 1024 + threadIdx.x;
    if (idx < N_NODES) g_ptr[idx] += pre;
    if (idx == 0) g_ptr[N_NODES] = N_EDGES;
}

__global__ void k_fill() {
    int e = blockIdx.x * blockDim.x + threadIdx.x;
    if (e >= N_EDGES) return;
    int c = g_c32[e];
    int r = g_r32[e];
    int pos = atomicAdd(&g_cur[c], 1);
    int idx = g_ptr[c] + pos;
    g_src[idx] = r;
    g_wn[idx] = g_dinv[r] * g_dinv[c];
}

// ---------------- tensor-core GEMM (3xTF32): Y = (A .* scale?) @ W ----------
// mma.sync.m16n8k8 tf32, split-precision (big+small) for ~fp32 accuracy.
// 256 threads = 8 warps as 2(M)x4(N); each warp: M64 x N32. Output -> fp16.

__device__ __forceinline__ unsigned f2tf(float x) {
    unsigned r;
    asm("cvt.rna.tf32.f32 %0, %1;" : "=r"(r) : "f"(x));
    return r;
}

__device__ __forceinline__ void mma_tf32(float* d, const unsigned* a, const unsigned* b) {
    asm volatile(
        "mma.sync.aligned.m16n8k8.row.col.f32.tf32.tf32.f32 "
        "{%0,%1,%2,%3}, {%4,%5,%6,%7}, {%8,%9}, {%0,%1,%2,%3};"
        : "+f"(d[0]), "+f"(d[1]), "+f"(d[2]), "+f"(d[3])
        : "r"(a[0]), "r"(a[1]), "r"(a[2]), "r"(a[3]), "r"(b[0]), "r"(b[1]));
}

#define AS_STRIDE 17
#define WS_STRIDE 132

__global__ void k_gemm_tc(const float* __restrict__ A, const float* __restrict__ scale,
                          const float* __restrict__ W, __half2* __restrict__ Y) {
    __shared__ float Ab[128 * AS_STRIDE];
    __shared__ float Al[128 * AS_STRIDE];
    __shared__ float Wb[16 * WS_STRIDE];
    __shared__ float Wl[16 * WS_STRIDE];

    int tid  = threadIdx.x;
    int lane = tid & 31;
    int wid  = tid >> 5;
    int wm   = wid >> 2;          // 0..1  (M split)
    int wn   = wid & 3;           // 0..3  (N split)
    int g    = lane >> 2;         // 0..7
    int t    = lane & 3;          // 0..3
    int row0 = blockIdx.x * 128;

    float acc[4][4][4];           // [mt][nt][reg]
#pragma unroll
    for (int mt = 0; mt < 4; mt++)
#pragma unroll
        for (int nt = 0; nt < 4; nt++)
#pragma unroll
            for (int r = 0; r < 4; r++) acc[mt][nt][r] = 0.f;

    for (int kt = 0; kt < 8; kt++) {
        // ---- stage A tile: 128 rows x 16 k (split big/small) ----
#pragma unroll
        for (int ii = 0; ii < 2; ii++) {
            int i  = tid + ii * 256;          // float4 index 0..511
            int r  = i >> 2;                  // 0..127
            int kq = (i & 3) * 4;             // 0,4,8,12
            float4 v = make_float4(0.f, 0.f, 0.f, 0.f);
            int gr = row0 + r;
            if (gr < N_NODES)
                v = *(const float4*)(A + (size_t)gr * HDIM + kt * 16 + kq);
            if (scale) {
                v.x *= scale[kt * 16 + kq];
                v.y *= scale[kt * 16 + kq + 1];
                v.z *= scale[kt * 16 + kq + 2];
                v.w *= scale[kt * 16 + kq + 3];
            }
            float* pb = Ab + r * AS_STRIDE + kq;
            float* pl = Al + r * AS_STRIDE + kq;
            unsigned bx = f2tf(v.x); pb[0] = __uint_as_float(bx); pl[0] = __uint_as_float(f2tf(v.x - __uint_as_float(bx)));
            unsigned by = f2tf(v.y); pb[1] = __uint_as_float(by); pl[1] = __uint_as_float(f2tf(v.y - __uint_as_float(by)));
            unsigned bz = f2tf(v.z); pb[2] = __uint_as_float(bz); pl[2] = __uint_as_float(f2tf(v.z - __uint_as_float(bz)));
            unsigned bw = f2tf(v.w); pb[3] = __uint_as_float(bw); pl[3] = __uint_as_float(f2tf(v.w - __uint_as_float(bw)));
        }
        // ---- stage W tile: 16 k-rows x 128 n (split big/small) ----
#pragma unroll
        for (int ii = 0; ii < 2; ii++) {
            int i  = tid + ii * 256;          // float4 index 0..511
            int kr = i >> 5;                  // 0..15
            int nq = (i & 31) * 4;            // 0..124
            float4 v = *(const float4*)(W + (size_t)(kt * 16 + kr) * HDIM + nq);
            float* pb = Wb + kr * WS_STRIDE + nq;
            float* pl = Wl + kr * WS_STRIDE + nq;
            unsigned bx = f2tf(v.x); pb[0] = __uint_as_float(bx); pl[0] = __uint_as_float(f2tf(v.x - __uint_as_float(bx)));
            unsigned by = f2tf(v.y); pb[1] = __uint_as_float(by); pl[1] = __uint_as_float(f2tf(v.y - __uint_as_float(by)));
            unsigned bz = f2tf(v.z); pb[2] = __uint_as_float(bz); pl[2] = __uint_as_float(f2tf(v.z - __uint_as_float(bz)));
            unsigned bw = f2tf(v.w); pb[3] = __uint_as_float(bw); pl[3] = __uint_as_float(f2tf(v.w - __uint_as_float(bw)));
        }
        __syncthreads();

#pragma unroll
        for (int ks = 0; ks < 2; ks++) {
            int k0 = ks * 8;
            unsigned afb[4][4], afl[4][4];
#pragma unroll
            for (int mt = 0; mt < 4; mt++) {
                int rb = wm * 64 + mt * 16;
                afb[mt][0] = __float_as_uint(Ab[(rb + g) * AS_STRIDE + k0 + t]);
                afb[mt][1] = __float_as_uint(Ab[(rb + g + 8) * AS_STRIDE + k0 + t]);
                afb[mt][2] = __float_as_uint(Ab[(rb + g) * AS_STRIDE + k0 + t + 4]);
                afb[mt][3] = __float_as_uint(Ab[(rb + g + 8) * AS_STRIDE + k0 + t + 4]);
                afl[mt][0] = __float_as_uint(Al[(rb + g) * AS_STRIDE + k0 + t]);
                afl[mt][1] = __float_as_uint(Al[(rb + g + 8) * AS_STRIDE + k0 + t]);
                afl[mt][2] = __float_as_uint(Al[(rb + g) * AS_STRIDE + k0 + t + 4]);
                afl[mt][3] = __float_as_uint(Al[(rb + g + 8) * AS_STRIDE + k0 + t + 4]);
            }
            unsigned bfb[4][2], bfl[4][2];
#pragma unroll
            for (int nt = 0; nt < 4; nt++) {
                int n0 = wn * 32 + nt * 8;
                bfb[nt][0] = __float_as_uint(Wb[(k0 + t) * WS_STRIDE + n0 + g]);
                bfb[nt][1] = __float_as_uint(Wb[(k0 + t + 4) * WS_STRIDE + n0 + g]);
                bfl[nt][0] = __float_as_uint(Wl[(k0 + t) * WS_STRIDE + n0 + g]);
                bfl[nt][1] = __float_as_uint(Wl[(k0 + t + 4) * WS_STRIDE + n0 + g]);
            }
#pragma unroll
            for (int mt = 0; mt < 4; mt++)
#pragma unroll
                for (int nt = 0; nt < 4; nt++) {
                    mma_tf32(acc[mt][nt], afb[mt], bfb[nt]);   // big*big
                    mma_tf32(acc[mt][nt], afb[mt], bfl[nt]);   // big*small
                    mma_tf32(acc[mt][nt], afl[mt], bfb[nt]);   // small*big
                }
        }
        __syncthreads();
    }

    // ---- epilogue: fp32 acc -> half2, one 4B store per mma pair ----
#pragma unroll
    for (int mt = 0; mt < 4; mt++) {
        int r1 = row0 + wm * 64 + mt * 16 + g;
        int r2 = r1 + 8;
#pragma unroll
        for (int nt = 0; nt < 4; nt++) {
            int ch = wn * 16 + nt * 4 + t;        // half2 column index (c/2)
            if (r1 < N_NODES)
                Y[(size_t)r1 * 64 + ch] = __floats2half2_rn(acc[mt][nt][0], acc[mt][nt][1]);
            if (r2 < N_NODES)
                Y[(size_t)r2 * 64 + ch] = __floats2half2_rn(acc[mt][nt][2], acc[mt][nt][3]);
        }
    }
}

// ---------------- aggregation: h[c] = gelu(sum_e wn*y[src] + dinv^2*y[c] + b)
__device__ __forceinline__ float gelu_exact(float v) {
    return 0.5f * v * (1.f + erff(v * 0.70710678118654752f));
}

__global__ void k_agg(const __half2* __restrict__ Y, const float* __restrict__ b,
                      float* __restrict__ H) {
    int gw = (blockIdx.x * blockDim.x + threadIdx.x) >> 5;   // node id (warp/node)
    if (gw >= N_NODES) return;
    int lane = threadIdx.x & 31;
    int c = gw;
    float dc = g_dinv[c];
    float sw = dc * dc;                       // self-loop weight
    uint2 su = *(const uint2*)(Y + (size_t)c * 64 + lane * 2);
    float2 s0 = __half22float2(*(__half2*)&su.x);
    float2 s1 = __half22float2(*(__half2*)&su.y);
    float4 acc = make_float4(sw * s0.x, sw * s0.y, sw * s1.x, sw * s1.y);

    int beg = g_ptr[c], end = g_ptr[c + 1];
    for (int base = beg; base < end; base += 32) {
        int i = base + lane;
        int s = (i < end) ? g_src[i] : 0;
        float w = (i < end) ? g_wn[i] : 0.f;
        int m = min(32, end - base);
#pragma unroll 4
        for (int j = 0; j < m; j++) {
            int   sj = __shfl_sync(0xffffffffu, s, j);
            float wj = __shfl_sync(0xffffffffu, w, j);
            uint2 u = *(const uint2*)(Y + (size_t)sj * 64 + lane * 2);
            float2 v0 = __half22float2(*(__half2*)&u.x);
            float2 v1 = __half22float2(*(__half2*)&u.y);
            acc.x += wj * v0.x; acc.y += wj * v0.y;
            acc.z += wj * v1.x; acc.w += wj * v1.y;
        }
    }
    const float4 bb = *(const float4*)(b + lane * 4);
    acc.x = gelu_exact(acc.x + bb.x);
    acc.y = gelu_exact(acc.y + bb.y);
    acc.z = gelu_exact(acc.z + bb.z);
    acc.w = gelu_exact(acc.w + bb.w);
    *(float4*)(H + (size_t)c * HDIM + lane * 4) = acc;
}

// ---------------- final: out = gelu(Y + lb1) @ lw2 + lb2 ------------------
__global__ void k_final(const __half2* __restrict__ Y, const float* __restrict__ lb1,
                        const float* __restrict__ lw2, const float* __restrict__ lb2,
                        float* __restrict__ out) {
    __shared__ float t[16 * 128];
    __shared__ float w2[128 * 16];
    __shared__ float sb1[128];
    __shared__ float sb2[16];
    int tid = threadIdx.x;
    int n0 = blockIdx.x * 16;

    for (int i = tid; i < 2048; i += 256) w2[i] = lw2[i];
    if (tid < 128) sb1[tid] = lb1[tid];
    if (tid < 16)  sb2[tid] = lb2[tid];
    __syncthreads();

    for (int i = tid; i < 1024; i += 256) {          // 1024 half2 = 2048 floats
        int n = i >> 6, fh = i & 63;
        float2 v = __half22float2(Y[(size_t)(n0 + n) * 64 + fh]);
        t[n * 128 + fh * 2]     = gelu_exact(v.x + sb1[fh * 2]);
        t[n * 128 + fh * 2 + 1] = gelu_exact(v.y + sb1[fh * 2 + 1]);
    }
    __syncthreads();

    int n = tid >> 4, c = tid & 15;
    float acc = sb2[c];
#pragma unroll 8
    for (int f = 0; f < 128; f++)
        acc += t[n * 128 + f] * w2[f * 16 + c];
    out[(size_t)(n0 + n) * CDIM + c] = acc;
}

// ---------------- launch ---------------------------------------------------
extern "C" void kernel_launch(void* const* d_in, const int* in_sizes, int n_in,
                              void* d_out, int out_size) {
    const float* x    = (const float*)d_in[0];
    const void*  edge = d_in[1];
    const float* imp  = (const float*)d_in[2];
    const float* W1   = (const float*)d_in[3];
    const float* b1   = (const float*)d_in[4];
    const float* W2   = (const float*)d_in[5];
    const float* b2   = (const float*)d_in[6];
    const float* W3   = (const float*)d_in[7];
    const float* b3   = (const float*)d_in[8];
    const float* lw1  = (const float*)d_in[9];
    const float* lb1  = (const float*)d_in[10];
    const float* lw2  = (const float*)d_in[11];
    const float* lb2  = (const float*)d_in[12];
    float* out = (float*)d_out;

    const int EB = (N_EDGES + 255) / 256;      // 3125
    const int NB = (N_NODES + 255) / 256;      // 196
    const int SB = (N_NODES + 1023) / 1024;    // 49
    const int GB = (N_NODES + 127) / 128;      // 391
    const int AB = (N_NODES + 3) / 4;          // 12500 (4 warps/block)
    const int FB = N_NODES / 16;               // 3125

    __half2* y; cudaGetSymbolAddress((void**)&y, g_y);
    float*   h; cudaGetSymbolAddress((void**)&h, g_h);

    // --- CSR build (once per launch; reused for all 3 conv layers) ---
    k_detect_init<<<NB, 256>>>((const int*)edge);
    k_convert_hist<<<EB, 256>>>(edge);
    k_scan1<<<SB, 1024>>>();
    k_scan3<<<SB, 1024>>>();
    k_fill<<<EB, 256>>>();

    // --- layer 1: (x*importance) @ W1 -> propagate + b1 + gelu ---
    k_gemm_tc<<<GB, 256>>>(x, imp, W1, y);
    k_agg<<<AB, 128>>>(y, b1, h);
    // --- layer 2 ---
    k_gemm_tc<<<GB, 256>>>(h, nullptr, W2, y);
    k_agg<<<AB, 128>>>(y, b2, h);
    // --- layer 3 ---
    k_gemm_tc<<<GB, 256>>>(h, nullptr, W3, y);
    k_agg<<<AB, 128>>>(y, b3, h);
    // --- head: gelu(h@lw1+lb1) @ lw2 + lb2 ---
    k_gemm_tc<<<GB, 256>>>(h, nullptr, lw1, y);
    k_final<<<FB, 256>>>(y, lb1, lw2, lb2, out);
}

// round 9
// speedup vs baseline: 1.6651x; 1.1826x over previous
#include <cuda_runtime.h>
#include <cuda_fp16.h>
#include <math.h>

#define N_NODES 50000
#define N_EDGES 800000
#define HDIM 128
#define CDIM 16

// ---------------- scratch (device globals; no allocation) ----------------
__device__ int   g_is64;
__device__ int   g_r32[N_EDGES];
__device__ int   g_c32[N_EDGES];
__device__ int   g_cnt[N_NODES];
__device__ int   g_cur[N_NODES];
__device__ int   g_ptr[N_NODES + 1];
__device__ int   g_bsum[64];
__device__ float g_dinv[N_NODES];
__device__ int   g_src[N_EDGES];
__device__ float g_wn[N_EDGES];
__device__ float g_Wb[4 * 16384];               // tf32 "big" splits of the 4 weight mats
__device__ float g_Wl[4 * 16384];               // tf32 "small" splits
__device__ __half2 g_y[(size_t)N_NODES * 64];   // GEMM output (fp16 messages)
__device__ __half2 g_h[(size_t)N_NODES * 64];   // activations (fp16)

__device__ __forceinline__ unsigned f2tf(float x) {
    unsigned r;
    asm("cvt.rna.tf32.f32 %0, %1;" : "=r"(r) : "f"(x));
    return r;
}

// ---------------- init: zero counters + detect dtype + split weights ------
// grid: 256 blocks x 256 (65536 threads covers 4*16384 weight elems and 50000 counters)
__global__ void k_init_split(const int* __restrict__ e,
                             const float* __restrict__ W1, const float* __restrict__ W2,
                             const float* __restrict__ W3, const float* __restrict__ lw1) {
    int idx = blockIdx.x * 256 + threadIdx.x;
    if (idx < N_NODES) { g_cnt[idx] = 0; g_cur[idx] = 0; }
    int m = idx >> 14, pos = idx & 16383;
    const float* p = (m == 0) ? W1 : (m == 1) ? W2 : (m == 2) ? W3 : lw1;
    float v = p[pos];
    unsigned big = f2tf(v);
    g_Wb[idx] = __uint_as_float(big);
    g_Wl[idx] = __uint_as_float(f2tf(v - __uint_as_float(big)));
    if (blockIdx.x == 0) {
        __shared__ int any;
        if (threadIdx.x == 0) any = 0;
        __syncthreads();
        int w = e[2 * threadIdx.x + 1];   // odd words zero <=> int64 indices
        if (w != 0) atomicOr(&any, 1);
        __syncthreads();
        if (threadIdx.x == 0) g_is64 = (any == 0) ? 1 : 0;
    }
}

// fused convert + histogram
__global__ void k_convert_hist(const void* __restrict__ edge) {
    int e = blockIdx.x * blockDim.x + threadIdx.x;
    if (e >= N_EDGES) return;
    int r, c;
    if (g_is64) {
        const long long* p = (const long long*)edge;
        r = (int)p[e];
        c = (int)p[N_EDGES + e];
    } else {
        const int* p = (const int*)edge;
        r = p[e];
        c = p[N_EDGES + e];
    }
    g_r32[e] = r;
    g_c32[e] = c;
    atomicAdd(&g_cnt[c], 1);
}

// block-local exclusive scan (+ dinv fused)
__global__ void k_scan1() {
    __shared__ int s[1024];
    int idx = blockIdx.x * 1024 + threadIdx.x;
    int v = (idx < N_NODES) ? g_cnt[idx] : 0;
    if (idx < N_NODES) g_dinv[idx] = rsqrtf((float)(v + 1));
    s[threadIdx.x] = v;
    __syncthreads();
    for (int off = 1; off < 1024; off <<= 1) {
        int t = (threadIdx.x >= off) ? s[threadIdx.x - off] : 0;
        __syncthreads();
        s[threadIdx.x] += t;
        __syncthreads();
    }
    if (idx < N_NODES) g_ptr[idx] = s[threadIdx.x] - v;
    if (threadIdx.x == 1023) g_bsum[blockIdx.x] = s[1023];
}

// add cross-block prefix
__global__ void k_scan3() {
    __shared__ int pre;
    if (threadIdx.x < 32) {
        int p = 0;
        for (int i = threadIdx.x; i < blockIdx.x; i += 32) p += g_bsum[i];
#pragma unroll
        for (int o = 16; o; o >>= 1) p += __shfl_xor_sync(0xffffffffu, p, o);
        if (threadIdx.x == 0) pre = p;
    }
    __syncthreads();
    int idx = blockIdx.x * 1024 + threadIdx.x;
    if (idx < N_NODES) g_ptr[idx] += pre;
    if (idx == 0) g_ptr[N_NODES] = N_EDGES;
}

__global__ void k_fill() {
    int e = blockIdx.x * blockDim.x + threadIdx.x;
    if (e >= N_EDGES) return;
    int c = g_c32[e];
    int r = g_r32[e];
    int pos = atomicAdd(&g_cur[c], 1);
    int idx = g_ptr[c] + pos;
    g_src[idx] = r;
    g_wn[idx] = g_dinv[r] * g_dinv[c];
}

// ---------------- tensor-core GEMM (split TF32) ----------------------------
// ATYPE 0: A fp32 with importance scale, 3-term (Ab*Bb + Ab*Bl + Al*Bb).
// ATYPE 1: A fp16 (exactly representable in tf32), 2-term (Ab*Bb + Ab*Bl).
// 256 threads = 8 warps 2(M)x4(N); warp tile M64xN32; K tiled by 16.

__device__ __forceinline__ void mma_tf32(float* d, const unsigned* a, const unsigned* b) {
    asm volatile(
        "mma.sync.aligned.m16n8k8.row.col.f32.tf32.tf32.f32 "
        "{%0,%1,%2,%3}, {%4,%5,%6,%7}, {%8,%9}, {%0,%1,%2,%3};"
        : "+f"(d[0]), "+f"(d[1]), "+f"(d[2]), "+f"(d[3])
        : "r"(a[0]), "r"(a[1]), "r"(a[2]), "r"(a[3]), "r"(b[0]), "r"(b[1]));
}

#define AS_STRIDE 17
#define WS_STRIDE 132

template <int ATYPE>
__global__ void k_gemm_tc(const void* __restrict__ Ap, const float* __restrict__ scale,
                          const float* __restrict__ Wb_, const float* __restrict__ Wl_,
                          __half2* __restrict__ Y) {
    __shared__ float Ab[128 * AS_STRIDE];
    __shared__ float Al[128 * AS_STRIDE];   // used only for ATYPE==0
    __shared__ float Wb[16 * WS_STRIDE];
    __shared__ float Wl[16 * WS_STRIDE];

    int tid  = threadIdx.x;
    int lane = tid & 31;
    int wid  = tid >> 5;
    int wm   = wid >> 2;
    int wn   = wid & 3;
    int g    = lane >> 2;
    int t    = lane & 3;
    int row0 = blockIdx.x * 128;

    float acc[4][4][4];
#pragma unroll
    for (int mt = 0; mt < 4; mt++)
#pragma unroll
        for (int nt = 0; nt < 4; nt++)
#pragma unroll
            for (int r = 0; r < 4; r++) acc[mt][nt][r] = 0.f;

    for (int kt = 0; kt < 8; kt++) {
        // ---- stage A tile ----
        if (ATYPE == 0) {
            const float* A = (const float*)Ap;
#pragma unroll
            for (int ii = 0; ii < 2; ii++) {
                int i  = tid + ii * 256;
                int r  = i >> 2;
                int kq = (i & 3) * 4;
                float4 v = make_float4(0.f, 0.f, 0.f, 0.f);
                int gr = row0 + r;
                if (gr < N_NODES)
                    v = *(const float4*)(A + (size_t)gr * HDIM + kt * 16 + kq);
                v.x *= scale[kt * 16 + kq];
                v.y *= scale[kt * 16 + kq + 1];
                v.z *= scale[kt * 16 + kq + 2];
                v.w *= scale[kt * 16 + kq + 3];
                float* pb = Ab + r * AS_STRIDE + kq;
                float* pl = Al + r * AS_STRIDE + kq;
                unsigned bx = f2tf(v.x); pb[0] = __uint_as_float(bx); pl[0] = __uint_as_float(f2tf(v.x - __uint_as_float(bx)));
                unsigned by = f2tf(v.y); pb[1] = __uint_as_float(by); pl[1] = __uint_as_float(f2tf(v.y - __uint_as_float(by)));
                unsigned bz = f2tf(v.z); pb[2] = __uint_as_float(bz); pl[2] = __uint_as_float(f2tf(v.z - __uint_as_float(bz)));
                unsigned bw = f2tf(v.w); pb[3] = __uint_as_float(bw); pl[3] = __uint_as_float(f2tf(v.w - __uint_as_float(bw)));
            }
        } else {
            // fp16 A: 128 rows x 16 halves; one uint4 (8 halves) per thread-slot
            const __half2* A = (const __half2*)Ap;
            int r = tid >> 1;
            int q = (tid & 1) * 8;               // half offset within the 16
            uint4 u = make_uint4(0, 0, 0, 0);
            int gr = row0 + r;
            if (gr < N_NODES)
                u = *(const uint4*)(A + (size_t)gr * 64 + kt * 8 + (q >> 1));
            float* pb = Ab + r * AS_STRIDE + q;
            float2 f0 = __half22float2(*(__half2*)&u.x);
            float2 f1 = __half22float2(*(__half2*)&u.y);
            float2 f2 = __half22float2(*(__half2*)&u.z);
            float2 f3 = __half22float2(*(__half2*)&u.w);
            pb[0] = f0.x; pb[1] = f0.y; pb[2] = f1.x; pb[3] = f1.y;
            pb[4] = f2.x; pb[5] = f2.y; pb[6] = f3.x; pb[7] = f3.y;
        }
        // ---- stage W tiles (pre-split; pure copies) ----
#pragma unroll
        for (int ii = 0; ii < 2; ii++) {
            int i  = tid + ii * 256;
            int kr = i >> 5;
            int nq = (i & 31) * 4;
            *(float4*)(Wb + kr * WS_STRIDE + nq) = *(const float4*)(Wb_ + (size_t)(kt * 16 + kr) * HDIM + nq);
            *(float4*)(Wl + kr * WS_STRIDE + nq) = *(const float4*)(Wl_ + (size_t)(kt * 16 + kr) * HDIM + nq);
        }
        __syncthreads();

#pragma unroll
        for (int ks = 0; ks < 2; ks++) {
            int k0 = ks * 8;
            unsigned afb[4][4], afl[4][4];
#pragma unroll
            for (int mt = 0; mt < 4; mt++) {
                int rb = wm * 64 + mt * 16;
                afb[mt][0] = __float_as_uint(Ab[(rb + g) * AS_STRIDE + k0 + t]);
                afb[mt][1] = __float_as_uint(Ab[(rb + g + 8) * AS_STRIDE + k0 + t]);
                afb[mt][2] = __float_as_uint(Ab[(rb + g) * AS_STRIDE + k0 + t + 4]);
                afb[mt][3] = __float_as_uint(Ab[(rb + g + 8) * AS_STRIDE + k0 + t + 4]);
                if (ATYPE == 0) {
                    afl[mt][0] = __float_as_uint(Al[(rb + g) * AS_STRIDE + k0 + t]);
                    afl[mt][1] = __float_as_uint(Al[(rb + g + 8) * AS_STRIDE + k0 + t]);
                    afl[mt][2] = __float_as_uint(Al[(rb + g) * AS_STRIDE + k0 + t + 4]);
                    afl[mt][3] = __float_as_uint(Al[(rb + g + 8) * AS_STRIDE + k0 + t + 4]);
                }
            }
            unsigned bfb[4][2], bfl[4][2];
#pragma unroll
            for (int nt = 0; nt < 4; nt++) {
                int n0 = wn * 32 + nt * 8;
                bfb[nt][0] = __float_as_uint(Wb[(k0 + t) * WS_STRIDE + n0 + g]);
                bfb[nt][1] = __float_as_uint(Wb[(k0 + t + 4) * WS_STRIDE + n0 + g]);
                bfl[nt][0] = __float_as_uint(Wl[(k0 + t) * WS_STRIDE + n0 + g]);
                bfl[nt][1] = __float_as_uint(Wl[(k0 + t + 4) * WS_STRIDE + n0 + g]);
            }
#pragma unroll
            for (int mt = 0; mt < 4; mt++)
#pragma unroll
                for (int nt = 0; nt < 4; nt++) {
                    mma_tf32(acc[mt][nt], afb[mt], bfb[nt]);
                    mma_tf32(acc[mt][nt], afb[mt], bfl[nt]);
                    if (ATYPE == 0) mma_tf32(acc[mt][nt], afl[mt], bfb[nt]);
                }
        }
        __syncthreads();
    }

#pragma unroll
    for (int mt = 0; mt < 4; mt++) {
        int r1 = row0 + wm * 64 + mt * 16 + g;
        int r2 = r1 + 8;
#pragma unroll
        for (int nt = 0; nt < 4; nt++) {
            int ch = wn * 16 + nt * 4 + t;
            if (r1 < N_NODES)
                Y[(size_t)r1 * 64 + ch] = __floats2half2_rn(acc[mt][nt][0], acc[mt][nt][1]);
            if (r2 < N_NODES)
                Y[(size_t)r2 * 64 + ch] = __floats2half2_rn(acc[mt][nt][2], acc[mt][nt][3]);
        }
    }
}

// ---------------- aggregation (shfl-free, 16 lanes/node) -------------------
__device__ __forceinline__ float gelu_exact(float v) {
    return 0.5f * v * (1.f + erff(v * 0.70710678118654752f));
}

__device__ __forceinline__ void fma8(float* acc, uint4 u, float w) {
    float2 a = __half22float2(*(__half2*)&u.x);
    float2 b = __half22float2(*(__half2*)&u.y);
    float2 c = __half22float2(*(__half2*)&u.z);
    float2 d = __half22float2(*(__half2*)&u.w);
    acc[0] += w * a.x; acc[1] += w * a.y;
    acc[2] += w * b.x; acc[3] += w * b.y;
    acc[4] += w * c.x; acc[5] += w * c.y;
    acc[6] += w * d.x; acc[7] += w * d.y;
}

__global__ void k_agg(const __half2* __restrict__ Y, const float* __restrict__ b,
                      __half2* __restrict__ H) {
    int tid  = threadIdx.x;
    int warp = tid >> 5;
    int lane = tid & 31;
    int sub  = lane & 15;                 // lane within 16-lane node group
    int c = blockIdx.x * 16 + warp * 2 + (lane >> 4);

    float dc = g_dinv[c];
    float sw = dc * dc;
    float acc[8] = {0, 0, 0, 0, 0, 0, 0, 0};
    fma8(acc, *(const uint4*)(Y + (size_t)c * 64 + sub * 4), sw);

    int beg = g_ptr[c], end = g_ptr[c + 1];
    int i = beg;
    for (; i + 4 <= end; i += 4) {
        int   s0 = g_src[i],     s1 = g_src[i + 1], s2 = g_src[i + 2], s3 = g_src[i + 3];
        float w0 = g_wn[i],      w1 = g_wn[i + 1],  w2 = g_wn[i + 2],  w3 = g_wn[i + 3];
        uint4 u0 = *(const uint4*)(Y + (size_t)s0 * 64 + sub * 4);
        uint4 u1 = *(const uint4*)(Y + (size_t)s1 * 64 + sub * 4);
        uint4 u2 = *(const uint4*)(Y + (size_t)s2 * 64 + sub * 4);
        uint4 u3 = *(const uint4*)(Y + (size_t)s3 * 64 + sub * 4);
        fma8(acc, u0, w0); fma8(acc, u1, w1); fma8(acc, u2, w2); fma8(acc, u3, w3);
    }
    for (; i < end; i++) {
        int   s = g_src[i];
        float w = g_wn[i];
        fma8(acc, *(const uint4*)(Y + (size_t)s * 64 + sub * 4), w);
    }

    const float4 b0 = *(const float4*)(b + sub * 8);
    const float4 b1 = *(const float4*)(b + sub * 8 + 4);
    uint4 o;
    __half2 h0 = __floats2half2_rn(gelu_exact(acc[0] + b0.x), gelu_exact(acc[1] + b0.y));
    __half2 h1 = __floats2half2_rn(gelu_exact(acc[2] + b0.z), gelu_exact(acc[3] + b0.w));
    __half2 h2 = __floats2half2_rn(gelu_exact(acc[4] + b1.x), gelu_exact(acc[5] + b1.y));
    __half2 h3 = __floats2half2_rn(gelu_exact(acc[6] + b1.z), gelu_exact(acc[7] + b1.w));
    o.x = *(unsigned*)&h0; o.y = *(unsigned*)&h1; o.z = *(unsigned*)&h2; o.w = *(unsigned*)&h3;
    *(uint4*)(H + (size_t)c * 64 + sub * 4) = o;
}

// ---------------- final: out = gelu(Y + lb1) @ lw2 + lb2 ------------------
__global__ void k_final(const __half2* __restrict__ Y, const float* __restrict__ lb1,
                        const float* __restrict__ lw2, const float* __restrict__ lb2,
                        float* __restrict__ out) {
    __shared__ float t[16 * 128];
    __shared__ float w2[128 * 16];
    __shared__ float sb1[128];
    __shared__ float sb2[16];
    int tid = threadIdx.x;
    int n0 = blockIdx.x * 16;

    for (int i = tid; i < 2048; i += 256) w2[i] = lw2[i];
    if (tid < 128) sb1[tid] = lb1[tid];
    if (tid < 16)  sb2[tid] = lb2[tid];
    __syncthreads();

    for (int i = tid; i < 1024; i += 256) {
        int n = i >> 6, fh = i & 63;
        float2 v = __half22float2(Y[(size_t)(n0 + n) * 64 + fh]);
        t[n * 128 + fh * 2]     = gelu_exact(v.x + sb1[fh * 2]);
        t[n * 128 + fh * 2 + 1] = gelu_exact(v.y + sb1[fh * 2 + 1]);
    }
    __syncthreads();

    int n = tid >> 4, c = tid & 15;
    float acc = sb2[c];
#pragma unroll 8
    for (int f = 0; f < 128; f++)
        acc += t[n * 128 + f] * w2[f * 16 + c];
    out[(size_t)(n0 + n) * CDIM + c] = acc;
}

// ---------------- launch ---------------------------------------------------
extern "C" void kernel_launch(void* const* d_in, const int* in_sizes, int n_in,
                              void* d_out, int out_size) {
    const float* x    = (const float*)d_in[0];
    const void*  edge = d_in[1];
    const float* imp  = (const float*)d_in[2];
    const float* W1   = (const float*)d_in[3];
    const float* b1   = (const float*)d_in[4];
    const float* W2   = (const float*)d_in[5];
    const float* b2   = (const float*)d_in[6];
    const float* W3   = (const float*)d_in[7];
    const float* b3   = (const float*)d_in[8];
    const float* lw1  = (const float*)d_in[9];
    const float* lb1  = (const float*)d_in[10];
    const float* lw2  = (const float*)d_in[11];
    const float* lb2  = (const float*)d_in[12];
    float* out = (float*)d_out;

    const int EB = (N_EDGES + 255) / 256;      // 3125
    const int SB = (N_NODES + 1023) / 1024;    // 49
    const int GB = (N_NODES + 127) / 128;      // 391
    const int AB = N_NODES / 16;               // 3125 (16 nodes/block, 256 thr)
    const int FB = N_NODES / 16;               // 3125

    __half2* y; cudaGetSymbolAddress((void**)&y, g_y);
    __half2* h; cudaGetSymbolAddress((void**)&h, g_h);
    float* wb; cudaGetSymbolAddress((void**)&wb, g_Wb);
    float* wl; cudaGetSymbolAddress((void**)&wl, g_Wl);

    // --- init + weight split + CSR build ---
    k_init_split<<<256, 256>>>((const int*)edge, W1, W2, W3, lw1);
    k_convert_hist<<<EB, 256>>>(edge);
    k_scan1<<<SB, 1024>>>();
    k_scan3<<<SB, 1024>>>();
    k_fill<<<EB, 256>>>();

    // --- layer 1 (fp32 A, 3-term) ---
    k_gemm_tc<0><<<GB, 256>>>(x, imp, wb, wl, y);
    k_agg<<<AB, 256>>>(y, b1, h);
    // --- layer 2 (fp16 A, 2-term) ---
    k_gemm_tc<1><<<GB, 256>>>(h, nullptr, wb + 16384, wl + 16384, y);
    k_agg<<<AB, 256>>>(y, b2, h);
    // --- layer 3 ---
    k_gemm_tc<1><<<GB, 256>>>(h, nullptr, wb + 2 * 16384, wl + 2 * 16384, y);
    k_agg<<<AB, 256>>>(y, b3, h);
    // --- head ---
    k_gemm_tc<1><<<GB, 256>>>(h, nullptr, wb + 3 * 16384, wl + 3 * 16384, y);
    k_final<<<FB, 256>>>(y, lb1, lw2, lb2, out);
}

// round 10
// speedup vs baseline: 2.1215x; 1.2741x over previous
#include <cuda_runtime.h>
#include <cuda_fp16.h>
#include <math.h>

#define N_NODES 50000
#define N_EDGES 800000
#define HDIM 128
#define CDIM 16

// ---------------- scratch (device globals; no allocation) ----------------
__device__ int   g_is64;
__device__ int   g_r32[N_EDGES];
__device__ int   g_c32[N_EDGES];
__device__ int   g_cnt[N_NODES];
__device__ int   g_cur[N_NODES];
__device__ int   g_ptr[N_NODES + 1];
__device__ int   g_bsum[64];
__device__ int   g_bflag[64];
__device__ float g_dinv[N_NODES];
__device__ int   g_src[N_EDGES];
__device__ float g_wn[N_EDGES];
__device__ float   g_W1b[16384];                 // tf32 split of W1 (layer 1)
__device__ float   g_W1l[16384];
__device__ __half2 g_Whf[3 * 8192 + 1024];       // fp16 "big" packs: W2,W3,lw1,lw2
__device__ __half2 g_Wlf[3 * 8192 + 1024];       // fp16 residual packs
__device__ __half2 g_y[(size_t)N_NODES * 64];    // GEMM output (fp16 messages)
__device__ __half2 g_h[(size_t)N_NODES * 64];    // activations (fp16)

__device__ __forceinline__ unsigned f2tf(float x) {
    unsigned r;
    asm("cvt.rna.tf32.f32 %0, %1;" : "=r"(r) : "f"(x));
    return r;
}

// ---------------- init: zero counters/flags + detect dtype + split weights --
// grid 256x256 = 65536 threads.
__global__ void k_init_split(const int* __restrict__ e,
                             const float* __restrict__ W1, const float* __restrict__ W2,
                             const float* __restrict__ W3, const float* __restrict__ lw1,
                             const float* __restrict__ lw2) {
    int idx = blockIdx.x * 256 + threadIdx.x;
    if (idx < N_NODES) { g_cnt[idx] = 0; g_cur[idx] = 0; }
    if (idx < 64) g_bflag[idx] = 0;

    if (idx < 16384) {
        float v = W1[idx];
        unsigned big = f2tf(v);
        g_W1b[idx] = __uint_as_float(big);
        g_W1l[idx] = __uint_as_float(f2tf(v - __uint_as_float(big)));
    } else if (idx < 40960) {
        int j = idx - 16384;                    // [mat][k2][n], 128-wide mats
        int m = j >> 13, r = j & 8191;
        int k2 = r >> 7, n = r & 127;
        const float* src = (m == 0) ? W2 : (m == 1) ? W3 : lw1;
        float w0 = src[(2 * k2) * 128 + n];
        float w1 = src[(2 * k2 + 1) * 128 + n];
        __half h0 = __float2half_rn(w0), h1 = __float2half_rn(w1);
        __half l0 = __float2half_rn(w0 - __half2float(h0));
        __half l1 = __float2half_rn(w1 - __half2float(h1));
        g_Whf[j] = __halves2half2(h0, h1);
        g_Wlf[j] = __halves2half2(l0, l1);
    } else if (idx < 41984) {
        int j = idx - 40960;                    // lw2: [k2][n], n=16
        int k2 = j >> 4, n = j & 15;
        float w0 = lw2[(2 * k2) * 16 + n];
        float w1 = lw2[(2 * k2 + 1) * 16 + n];
        __half h0 = __float2half_rn(w0), h1 = __float2half_rn(w1);
        __half l0 = __float2half_rn(w0 - __half2float(h0));
        __half l1 = __float2half_rn(w1 - __half2float(h1));
        g_Whf[24576 + j] = __halves2half2(h0, h1);
        g_Wlf[24576 + j] = __halves2half2(l0, l1);
    }

    if (blockIdx.x == 0) {
        __shared__ int any;
        if (threadIdx.x == 0) any = 0;
        __syncthreads();
        int w = e[2 * threadIdx.x + 1];   // odd words zero <=> int64 indices
        if (w != 0) atomicOr(&any, 1);
        __syncthreads();
        if (threadIdx.x == 0) g_is64 = (any == 0) ? 1 : 0;
    }
}

// fused convert + histogram
__global__ void k_convert_hist(const void* __restrict__ edge) {
    int e = blockIdx.x * blockDim.x + threadIdx.x;
    if (e >= N_EDGES) return;
    int r, c;
    if (g_is64) {
        const long long* p = (const long long*)edge;
        r = (int)p[e];
        c = (int)p[N_EDGES + e];
    } else {
        const int* p = (const int*)edge;
        r = p[e];
        c = p[N_EDGES + e];
    }
    g_r32[e] = r;
    g_c32[e] = c;
    atomicAdd(&g_cnt[c], 1);
}

// single-pass exclusive scan with decoupled lookback (+ dinv fused)
__global__ void k_scan() {
    __shared__ int s[1024];
    __shared__ int pre;
    int idx = blockIdx.x * 1024 + threadIdx.x;
    int v = (idx < N_NODES) ? g_cnt[idx] : 0;
    if (idx < N_NODES) g_dinv[idx] = rsqrtf((float)(v + 1));
    s[threadIdx.x] = v;
    __syncthreads();
    for (int off = 1; off < 1024; off <<= 1) {
        int t = (threadIdx.x >= off) ? s[threadIdx.x - off] : 0;
        __syncthreads();
        s[threadIdx.x] += t;
        __syncthreads();
    }
    if (threadIdx.x == 1023) {
        g_bsum[blockIdx.x] = s[1023];
        __threadfence();
        atomicExch(&g_bflag[blockIdx.x], 1);
    }
    if (threadIdx.x < 32) {
        int p = 0;
        for (int i = threadIdx.x; i < blockIdx.x; i += 32) {
            while (atomicAdd(&g_bflag[i], 0) == 0) {}
            p += atomicAdd(&g_bsum[i], 0);
        }
#pragma unroll
        for (int o = 16; o; o >>= 1) p += __shfl_xor_sync(0xffffffffu, p, o);
        if (threadIdx.x == 0) pre = p;
    }
    __syncthreads();
    if (idx < N_NODES) g_ptr[idx] = s[threadIdx.x] - v + pre;
    if (idx == 0) g_ptr[N_NODES] = N_EDGES;
}

__global__ void k_fill() {
    int e = blockIdx.x * blockDim.x + threadIdx.x;
    if (e >= N_EDGES) return;
    int c = g_c32[e];
    int r = g_r32[e];
    int pos = atomicAdd(&g_cur[c], 1);
    int idx = g_ptr[c] + pos;
    g_src[idx] = r;
    g_wn[idx] = g_dinv[r] * g_dinv[c];
}

// ---------------- mma wrappers ---------------------------------------------
__device__ __forceinline__ void mma_tf32(float* d, const unsigned* a, const unsigned* b) {
    asm volatile(
        "mma.sync.aligned.m16n8k8.row.col.f32.tf32.tf32.f32 "
        "{%0,%1,%2,%3}, {%4,%5,%6,%7}, {%8,%9}, {%0,%1,%2,%3};"
        : "+f"(d[0]), "+f"(d[1]), "+f"(d[2]), "+f"(d[3])
        : "r"(a[0]), "r"(a[1]), "r"(a[2]), "r"(a[3]), "r"(b[0]), "r"(b[1]));
}

__device__ __forceinline__ void mma_f16(float* d, const unsigned* a, const unsigned* b) {
    asm volatile(
        "mma.sync.aligned.m16n8k16.row.col.f32.f16.f16.f32 "
        "{%0,%1,%2,%3}, {%4,%5,%6,%7}, {%8,%9}, {%0,%1,%2,%3};"
        : "+f"(d[0]), "+f"(d[1]), "+f"(d[2]), "+f"(d[3])
        : "r"(a[0]), "r"(a[1]), "r"(a[2]), "r"(a[3]), "r"(b[0]), "r"(b[1]));
}

__device__ __forceinline__ float gelu_exact(float v) {
    return 0.5f * v * (1.f + erff(v * 0.70710678118654752f));
}

// ---------------- layer-1 GEMM (fp32 A, 3-term tf32) -----------------------
#define AS_STRIDE 17
#define WS_STRIDE 132

__global__ void k_gemm_l1(const float* __restrict__ A, const float* __restrict__ scale,
                          const float* __restrict__ Wb_, const float* __restrict__ Wl_,
                          __half2* __restrict__ Y) {
    __shared__ float Ab[128 * AS_STRIDE];
    __shared__ float Al[128 * AS_STRIDE];
    __shared__ float Wb[16 * WS_STRIDE];
    __shared__ float Wl[16 * WS_STRIDE];

    int tid  = threadIdx.x;
    int lane = tid & 31;
    int wid  = tid >> 5;
    int wm   = wid >> 2;
    int wn   = wid & 3;
    int g    = lane >> 2;
    int t    = lane & 3;
    int row0 = blockIdx.x * 128;

    float acc[4][4][4];
#pragma unroll
    for (int mt = 0; mt < 4; mt++)
#pragma unroll
        for (int nt = 0; nt < 4; nt++)
#pragma unroll
            for (int r = 0; r < 4; r++) acc[mt][nt][r] = 0.f;

    for (int kt = 0; kt < 8; kt++) {
#pragma unroll
        for (int ii = 0; ii < 2; ii++) {
            int i  = tid + ii * 256;
            int r  = i >> 2;
            int kq = (i & 3) * 4;
            float4 v = make_float4(0.f, 0.f, 0.f, 0.f);
            int gr = row0 + r;
            if (gr < N_NODES)
                v = *(const float4*)(A + (size_t)gr * HDIM + kt * 16 + kq);
            v.x *= scale[kt * 16 + kq];
            v.y *= scale[kt * 16 + kq + 1];
            v.z *= scale[kt * 16 + kq + 2];
            v.w *= scale[kt * 16 + kq + 3];
            float* pb = Ab + r * AS_STRIDE + kq;
            float* pl = Al + r * AS_STRIDE + kq;
            unsigned bx = f2tf(v.x); pb[0] = __uint_as_float(bx); pl[0] = __uint_as_float(f2tf(v.x - __uint_as_float(bx)));
            unsigned by = f2tf(v.y); pb[1] = __uint_as_float(by); pl[1] = __uint_as_float(f2tf(v.y - __uint_as_float(by)));
            unsigned bz = f2tf(v.z); pb[2] = __uint_as_float(bz); pl[2] = __uint_as_float(f2tf(v.z - __uint_as_float(bz)));
            unsigned bw = f2tf(v.w); pb[3] = __uint_as_float(bw); pl[3] = __uint_as_float(f2tf(v.w - __uint_as_float(bw)));
        }
#pragma unroll
        for (int ii = 0; ii < 2; ii++) {
            int i  = tid + ii * 256;
            int kr = i >> 5;
            int nq = (i & 31) * 4;
            *(float4*)(Wb + kr * WS_STRIDE + nq) = *(const float4*)(Wb_ + (size_t)(kt * 16 + kr) * HDIM + nq);
            *(float4*)(Wl + kr * WS_STRIDE + nq) = *(const float4*)(Wl_ + (size_t)(kt * 16 + kr) * HDIM + nq);
        }
        __syncthreads();

#pragma unroll
        for (int ks = 0; ks < 2; ks++) {
            int k0 = ks * 8;
            unsigned afb[4][4], afl[4][4];
#pragma unroll
            for (int mt = 0; mt < 4; mt++) {
                int rb = wm * 64 + mt * 16;
                afb[mt][0] = __float_as_uint(Ab[(rb + g) * AS_STRIDE + k0 + t]);
                afb[mt][1] = __float_as_uint(Ab[(rb + g + 8) * AS_STRIDE + k0 + t]);
                afb[mt][2] = __float_as_uint(Ab[(rb + g) * AS_STRIDE + k0 + t + 4]);
                afb[mt][3] = __float_as_uint(Ab[(rb + g + 8) * AS_STRIDE + k0 + t + 4]);
                afl[mt][0] = __float_as_uint(Al[(rb + g) * AS_STRIDE + k0 + t]);
                afl[mt][1] = __float_as_uint(Al[(rb + g + 8) * AS_STRIDE + k0 + t]);
                afl[mt][2] = __float_as_uint(Al[(rb + g) * AS_STRIDE + k0 + t + 4]);
                afl[mt][3] = __float_as_uint(Al[(rb + g + 8) * AS_STRIDE + k0 + t + 4]);
            }
            unsigned bfb[4][2], bfl[4][2];
#pragma unroll
            for (int nt = 0; nt < 4; nt++) {
                int n0 = wn * 32 + nt * 8;
                bfb[nt][0] = __float_as_uint(Wb[(k0 + t) * WS_STRIDE + n0 + g]);
                bfb[nt][1] = __float_as_uint(Wb[(k0 + t + 4) * WS_STRIDE + n0 + g]);
                bfl[nt][0] = __float_as_uint(Wl[(k0 + t) * WS_STRIDE + n0 + g]);
                bfl[nt][1] = __float_as_uint(Wl[(k0 + t + 4) * WS_STRIDE + n0 + g]);
            }
#pragma unroll
            for (int mt = 0; mt < 4; mt++)
#pragma unroll
                for (int nt = 0; nt < 4; nt++) {
                    mma_tf32(acc[mt][nt], afb[mt], bfb[nt]);
                    mma_tf32(acc[mt][nt], afb[mt], bfl[nt]);
                    mma_tf32(acc[mt][nt], afl[mt], bfb[nt]);
                }
        }
        __syncthreads();
    }

#pragma unroll
    for (int mt = 0; mt < 4; mt++) {
        int r1 = row0 + wm * 64 + mt * 16 + g;
        int r2 = r1 + 8;
#pragma unroll
        for (int nt = 0; nt < 4; nt++) {
            int ch = wn * 16 + nt * 4 + t;
            if (r1 < N_NODES)
                Y[(size_t)r1 * 64 + ch] = __floats2half2_rn(acc[mt][nt][0], acc[mt][nt][1]);
            if (r2 < N_NODES)
                Y[(size_t)r2 * 64 + ch] = __floats2half2_rn(acc[mt][nt][2], acc[mt][nt][3]);
        }
    }
}

// ---------------- fp16 HMMA GEMM (layers 2/3; FINAL fuses head projection) --
// A fp16 (exact), W = Wh + Wl fp16 split, 2-term m16n8k16. 8 warps 2(M)x4(N).
#define AHS 20     // half2 stride of A smem row
#define WHS 136    // half2 stride of W smem k2-row
#define TSS 68     // half2 stride of fused-final T tile row
#define W2S 20     // half2 stride of lw2 smem k2-row

template <int FINAL>
__global__ void k_gemm_f16(const __half2* __restrict__ A,
                           const __half2* __restrict__ Wh_, const __half2* __restrict__ Wl_,
                           __half2* __restrict__ Y,
                           const float* __restrict__ lb1,
                           const __half2* __restrict__ W2h_, const __half2* __restrict__ W2l_,
                           const float* __restrict__ lb2, float* __restrict__ out) {
    extern __shared__ unsigned char smraw[];
    __half2* As  = (__half2*)smraw;                    // 128*AHS  (10240 B)
    __half2* Whs = (__half2*)(smraw + 10240);          // 16*WHS   (8704 B)
    __half2* Wls = (__half2*)(smraw + 18944);          // 16*WHS   (8704 B)

    int tid = threadIdx.x, lane = tid & 31, wid = tid >> 5;
    int wm = wid >> 2, wn = wid & 3;
    int g = lane >> 2, t4 = lane & 3;
    int row0 = blockIdx.x * 128;

    float acc[4][4][4];
#pragma unroll
    for (int mt = 0; mt < 4; mt++)
#pragma unroll
        for (int nt = 0; nt < 4; nt++)
#pragma unroll
            for (int r = 0; r < 4; r++) acc[mt][nt][r] = 0.f;

    int ar = tid >> 1, part = tid & 1;
    int wkr = tid >> 4, wnq = (tid & 15) * 8;

    for (int kt = 0; kt < 4; kt++) {
        // global loads first (latency overlap with the sync)
        uint4 au0 = make_uint4(0, 0, 0, 0), au1 = au0;
        {
            int gr = row0 + ar;
            if (gr < N_NODES) {
                const uint4* p = (const uint4*)(A + (size_t)gr * 64 + kt * 16 + part * 8);
                au0 = p[0]; au1 = p[1];
            }
        }
        const uint4* ph = (const uint4*)(Wh_ + (size_t)(kt * 16 + wkr) * 128 + wnq);
        const uint4* pl = (const uint4*)(Wl_ + (size_t)(kt * 16 + wkr) * 128 + wnq);
        uint4 wh0 = ph[0], wh1 = ph[1];
        uint4 wl0 = pl[0], wl1 = pl[1];

        __syncthreads();   // prior iteration's mma reads complete
        {
            uint4* q = (uint4*)(As + ar * AHS + part * 8);
            q[0] = au0; q[1] = au1;
            uint4* qh = (uint4*)(Whs + wkr * WHS + wnq);
            qh[0] = wh0; qh[1] = wh1;
            uint4* ql = (uint4*)(Wls + wkr * WHS + wnq);
            ql[0] = wl0; ql[1] = wl1;
        }
        __syncthreads();

#pragma unroll
        for (int ks = 0; ks < 2; ks++) {
            int kb = ks * 8;
            unsigned a[4][4];
#pragma unroll
            for (int mt = 0; mt < 4; mt++) {
                int rb = wm * 64 + mt * 16;
                a[mt][0] = *(unsigned*)&As[(rb + g) * AHS + kb + t4];
                a[mt][1] = *(unsigned*)&As[(rb + g + 8) * AHS + kb + t4];
                a[mt][2] = *(unsigned*)&As[(rb + g) * AHS + kb + t4 + 4];
                a[mt][3] = *(unsigned*)&As[(rb + g + 8) * AHS + kb + t4 + 4];
            }
            unsigned bh[4][2], bl[4][2];
#pragma unroll
            for (int nt = 0; nt < 4; nt++) {
                int n0 = wn * 32 + nt * 8;
                bh[nt][0] = *(unsigned*)&Whs[(kb + t4) * WHS + n0 + g];
                bh[nt][1] = *(unsigned*)&Whs[(kb + t4 + 4) * WHS + n0 + g];
                bl[nt][0] = *(unsigned*)&Wls[(kb + t4) * WHS + n0 + g];
                bl[nt][1] = *(unsigned*)&Wls[(kb + t4 + 4) * WHS + n0 + g];
            }
#pragma unroll
            for (int mt = 0; mt < 4; mt++)
#pragma unroll
                for (int nt = 0; nt < 4; nt++) {
                    mma_f16(acc[mt][nt], a[mt], bh[nt]);
                    mma_f16(acc[mt][nt], a[mt], bl[nt]);
                }
        }
    }

    if (FINAL == 0) {
#pragma unroll
        for (int mt = 0; mt < 4; mt++) {
            int r1 = row0 + wm * 64 + mt * 16 + g;
            int r2 = r1 + 8;
#pragma unroll
            for (int nt = 0; nt < 4; nt++) {
                int ch = wn * 16 + nt * 4 + t4;
                if (r1 < N_NODES)
                    Y[(size_t)r1 * 64 + ch] = __floats2half2_rn(acc[mt][nt][0], acc[mt][nt][1]);
                if (r2 < N_NODES)
                    Y[(size_t)r2 * 64 + ch] = __floats2half2_rn(acc[mt][nt][2], acc[mt][nt][3]);
            }
        }
    } else {
        // fused head: T = gelu(acc + lb1) in smem (aliases staging bufs), then T @ lw2
        __half2* Ts   = (__half2*)smraw;                 // 128*TSS  (34816 B)
        __half2* W2hs = (__half2*)(smraw + 34816);       // 64*W2S   (5120 B)
        __half2* W2ls = (__half2*)(smraw + 39936);       // 64*W2S   (5120 B)
        __syncthreads();                                 // all mma reads done
        // stage lw2 packs (1024 half2 each): one uint4 per thread
        {
            int k2 = tid >> 2, n4 = (tid & 3) * 4;
            *(uint4*)(W2hs + k2 * W2S + n4) = ((const uint4*)W2h_)[tid];
            *(uint4*)(W2ls + k2 * W2S + n4) = ((const uint4*)W2l_)[tid];
        }
#pragma unroll
        for (int mt = 0; mt < 4; mt++) {
            int rl1 = wm * 64 + mt * 16 + g;
            int rl2 = rl1 + 8;
#pragma unroll
            for (int nt = 0; nt < 4; nt++) {
                int c = wn * 32 + nt * 8 + 2 * t4;
                int ch = c >> 1;
                float2 lb = *(const float2*)(lb1 + c);
                Ts[rl1 * TSS + ch] = __floats2half2_rn(gelu_exact(acc[mt][nt][0] + lb.x),
                                                       gelu_exact(acc[mt][nt][1] + lb.y));
                Ts[rl2 * TSS + ch] = __floats2half2_rn(gelu_exact(acc[mt][nt][2] + lb.x),
                                                       gelu_exact(acc[mt][nt][3] + lb.y));
            }
        }
        __syncthreads();
        // phase 2: warp wid handles rows wid*16..wid*16+15 of the 128-row tile
        int rb2 = wid * 16;
        float f2[2][4];
#pragma unroll
        for (int n2 = 0; n2 < 2; n2++)
#pragma unroll
            for (int r = 0; r < 4; r++) f2[n2][r] = 0.f;
#pragma unroll
        for (int kq = 0; kq < 8; kq++) {
            unsigned a[4];
            a[0] = *(unsigned*)&Ts[(rb2 + g) * TSS + kq * 8 + t4];
            a[1] = *(unsigned*)&Ts[(rb2 + g + 8) * TSS + kq * 8 + t4];
            a[2] = *(unsigned*)&Ts[(rb2 + g) * TSS + kq * 8 + t4 + 4];
            a[3] = *(unsigned*)&Ts[(rb2 + g + 8) * TSS + kq * 8 + t4 + 4];
#pragma unroll
            for (int n2 = 0; n2 < 2; n2++) {
                unsigned bh[2], bl[2];
                bh[0] = *(unsigned*)&W2hs[(kq * 8 + t4) * W2S + n2 * 8 + g];
                bh[1] = *(unsigned*)&W2hs[(kq * 8 + t4 + 4) * W2S + n2 * 8 + g];
                bl[0] = *(unsigned*)&W2ls[(kq * 8 + t4) * W2S + n2 * 8 + g];
                bl[1] = *(unsigned*)&W2ls[(kq * 8 + t4 + 4) * W2S + n2 * 8 + g];
                mma_f16(f2[n2], a, bh);
                mma_f16(f2[n2], a, bl);
            }
        }
        int r1 = row0 + rb2 + g, r2 = r1 + 8;
#pragma unroll
        for (int n2 = 0; n2 < 2; n2++) {
            int c = n2 * 8 + 2 * t4;
            float2 lb = *(const float2*)(lb2 + c);
            if (r1 < N_NODES)
                *(float2*)(out + (size_t)r1 * CDIM + c) = make_float2(f2[n2][0] + lb.x, f2[n2][1] + lb.y);
            if (r2 < N_NODES)
                *(float2*)(out + (size_t)r2 * CDIM + c) = make_float2(f2[n2][2] + lb.x, f2[n2][3] + lb.y);
        }
    }
}

// ---------------- aggregation (shfl-free, 16 lanes/node) -------------------
__device__ __forceinline__ void fma8(float* acc, uint4 u, float w) {
    float2 a = __half22float2(*(__half2*)&u.x);
    float2 b = __half22float2(*(__half2*)&u.y);
    float2 c = __half22float2(*(__half2*)&u.z);
    float2 d = __half22float2(*(__half2*)&u.w);
    acc[0] += w * a.x; acc[1] += w * a.y;
    acc[2] += w * b.x; acc[3] += w * b.y;
    acc[4] += w * c.x; acc[5] += w * c.y;
    acc[6] += w * d.x; acc[7] += w * d.y;
}

__global__ void k_agg(const __half2* __restrict__ Y, const float* __restrict__ b,
                      __half2* __restrict__ H) {
    int tid  = threadIdx.x;
    int warp = tid >> 5;
    int lane = tid & 31;
    int sub  = lane & 15;
    int c = blockIdx.x * 16 + warp * 2 + (lane >> 4);

    float dc = g_dinv[c];
    float sw = dc * dc;
    float acc[8] = {0, 0, 0, 0, 0, 0, 0, 0};
    fma8(acc, *(const uint4*)(Y + (size_t)c * 64 + sub * 4), sw);

    int beg = g_ptr[c], end = g_ptr[c + 1];
    int i = beg;
    for (; i + 4 <= end; i += 4) {
        int   s0 = g_src[i],     s1 = g_src[i + 1], s2 = g_src[i + 2], s3 = g_src[i + 3];
        float w0 = g_wn[i],      w1 = g_wn[i + 1],  w2 = g_wn[i + 2],  w3 = g_wn[i + 3];
        uint4 u0 = *(const uint4*)(Y + (size_t)s0 * 64 + sub * 4);
        uint4 u1 = *(const uint4*)(Y + (size_t)s1 * 64 + sub * 4);
        uint4 u2 = *(const uint4*)(Y + (size_t)s2 * 64 + sub * 4);
        uint4 u3 = *(const uint4*)(Y + (size_t)s3 * 64 + sub * 4);
        fma8(acc, u0, w0); fma8(acc, u1, w1); fma8(acc, u2, w2); fma8(acc, u3, w3);
    }
    for (; i < end; i++) {
        int   s = g_src[i];
        float w = g_wn[i];
        fma8(acc, *(const uint4*)(Y + (size_t)s * 64 + sub * 4), w);
    }

    const float4 b0 = *(const float4*)(b + sub * 8);
    const float4 b1 = *(const float4*)(b + sub * 8 + 4);
    uint4 o;
    __half2 h0 = __floats2half2_rn(gelu_exact(acc[0] + b0.x), gelu_exact(acc[1] + b0.y));
    __half2 h1 = __floats2half2_rn(gelu_exact(acc[2] + b0.z), gelu_exact(acc[3] + b0.w));
    __half2 h2 = __floats2half2_rn(gelu_exact(acc[4] + b1.x), gelu_exact(acc[5] + b1.y));
    __half2 h3 = __floats2half2_rn(gelu_exact(acc[6] + b1.z), gelu_exact(acc[7] + b1.w));
    o.x = *(unsigned*)&h0; o.y = *(unsigned*)&h1; o.z = *(unsigned*)&h2; o.w = *(unsigned*)&h3;
    *(uint4*)(H + (size_t)c * 64 + sub * 4) = o;
}

// ---------------- launch ---------------------------------------------------
extern "C" void kernel_launch(void* const* d_in, const int* in_sizes, int n_in,
                              void* d_out, int out_size) {
    const float* x    = (const float*)d_in[0];
    const void*  edge = d_in[1];
    const float* imp  = (const float*)d_in[2];
    const float* W1   = (const float*)d_in[3];
    const float* b1   = (const float*)d_in[4];
    const float* W2   = (const float*)d_in[5];
    const float* b2   = (const float*)d_in[6];
    const float* W3   = (const float*)d_in[7];
    const float* b3   = (const float*)d_in[8];
    const float* lw1  = (const float*)d_in[9];
    const float* lb1  = (const float*)d_in[10];
    const float* lw2  = (const float*)d_in[11];
    const float* lb2  = (const float*)d_in[12];
    float* out = (float*)d_out;

    const int EB = (N_EDGES + 255) / 256;      // 3125
    const int SB = (N_NODES + 1023) / 1024;    // 49
    const int GB = (N_NODES + 127) / 128;      // 391
    const int AB = N_NODES / 16;               // 3125

    __half2* y; cudaGetSymbolAddress((void**)&y, g_y);
    __half2* h; cudaGetSymbolAddress((void**)&h, g_h);
    float* w1b; cudaGetSymbolAddress((void**)&w1b, g_W1b);
    float* w1l; cudaGetSymbolAddress((void**)&w1l, g_W1l);
    __half2* wh; cudaGetSymbolAddress((void**)&wh, g_Whf);
    __half2* wl; cudaGetSymbolAddress((void**)&wl, g_Wlf);

    const int SM_MAIN = 27648;   // As + Wh + Wl
    const int SM_FIN  = 45056;   // Ts + W2h + W2l overlay

    // --- init + weight split/pack + CSR build ---
    k_init_split<<<256, 256>>>((const int*)edge, W1, W2, W3, lw1, lw2);
    k_convert_hist<<<EB, 256>>>(edge);
    k_scan<<<SB, 1024>>>();
    k_fill<<<EB, 256>>>();

    // --- layer 1 (fp32 A, 3-term tf32) ---
    k_gemm_l1<<<GB, 256>>>(x, imp, w1b, w1l, y);
    k_agg<<<AB, 256>>>(y, b1, h);
    // --- layer 2 (fp16 A, 2-term fp16) ---
    k_gemm_f16<0><<<GB, 256, SM_MAIN>>>(h, wh, wl, y, nullptr, nullptr, nullptr, nullptr, nullptr);
    k_agg<<<AB, 256>>>(y, b2, h);
    // --- layer 3 ---
    k_gemm_f16<0><<<GB, 256, SM_MAIN>>>(h, wh + 8192, wl + 8192, y, nullptr, nullptr, nullptr, nullptr, nullptr);
    k_agg<<<AB, 256>>>(y, b3, h);
    // --- head (fused: gelu(h@lw1+lb1) @ lw2 + lb2 -> out) ---
    k_gemm_f16<1><<<GB, 256, SM_FIN>>>(h, wh + 16384, wl + 16384, nullptr, lb1,
                                       wh + 24576, wl + 24576, lb2, out);
}

// round 12
// speedup vs baseline: 2.3790x; 1.1214x over previous
#include <cuda_runtime.h>
#include <cuda_fp16.h>
#include <math.h>

#define N_NODES 50000
#define N_EDGES 800000
#define HDIM 128
#define CDIM 16

// ---------------- scratch (device globals; no allocation) ----------------
__device__ int   g_is64;
__device__ int2  g_rc[N_EDGES];                  // packed (row, col)
__device__ int   g_cnt[N_NODES];                 // degree; consumed by fill
__device__ int   g_ptr[N_NODES + 1];
__device__ int   g_bsum[64];
__device__ int   g_bflag[64];
__device__ float g_dinv[N_NODES];
__device__ int2  g_edge[N_EDGES];                // CSR: (src, wn-as-bits)
__device__ __half2 g_Whf[4 * 8192 + 1024];       // fp16 "big": W1,W2,W3,lw1,lw2
__device__ __half2 g_Wlf[4 * 8192 + 1024];       // fp16 residuals
__device__ __half2 g_y[(size_t)N_NODES * 64];    // GEMM output (fp16 messages)
__device__ __half2 g_h[(size_t)N_NODES * 64];    // activations (fp16)

// ---------------- init: counters + dtype detect + weight packs + x->fp16 ---
// grid 256 x 256 = 65536 threads
__global__ void k_init(const int* __restrict__ e,
                       const float* __restrict__ W1, const float* __restrict__ W2,
                       const float* __restrict__ W3, const float* __restrict__ lw1,
                       const float* __restrict__ lw2,
                       const float* __restrict__ x, const float* __restrict__ imp) {
    int idx = blockIdx.x * 256 + threadIdx.x;
    if (idx < N_NODES) g_cnt[idx] = 0;
    if (idx < 64) g_bflag[idx] = 0;

    if (idx < 32768) {                           // 4 mats x 8192 (k2,n) half2 packs
        int m = idx >> 13, r = idx & 8191;
        int k2 = r >> 7, n = r & 127;
        const float* src = (m == 0) ? W1 : (m == 1) ? W2 : (m == 2) ? W3 : lw1;
        float w0 = src[(2 * k2) * 128 + n];
        float w1 = src[(2 * k2 + 1) * 128 + n];
        __half h0 = __float2half_rn(w0), h1 = __float2half_rn(w1);
        g_Whf[idx] = __halves2half2(h0, h1);
        g_Wlf[idx] = __halves2half2(__float2half_rn(w0 - __half2float(h0)),
                                    __float2half_rn(w1 - __half2float(h1)));
    } else if (idx < 33792) {                    // lw2: 1024 (k2,n) packs
        int j = idx - 32768;
        int k2 = j >> 4, n = j & 15;
        float w0 = lw2[(2 * k2) * 16 + n];
        float w1 = lw2[(2 * k2 + 1) * 16 + n];
        __half h0 = __float2half_rn(w0), h1 = __float2half_rn(w1);
        g_Whf[32768 + j] = __halves2half2(h0, h1);
        g_Wlf[32768 + j] = __halves2half2(__float2half_rn(w0 - __half2float(h0)),
                                          __float2half_rn(w1 - __half2float(h1)));
    }

    // x * importance -> fp16 into g_h  (800000 uint4 = 50000 rows x 16 segs)
    for (int j = idx; j < N_NODES * 16; j += 65536) {
        int row = j >> 4, seg = j & 15;
        const float4* px = (const float4*)(x + (size_t)row * HDIM + seg * 8);
        float4 a = px[0], b = px[1];
        const float4* pi = (const float4*)(imp + seg * 8);
        float4 i0 = pi[0], i1 = pi[1];
        __half2 h0 = __floats2half2_rn(a.x * i0.x, a.y * i0.y);
        __half2 h1 = __floats2half2_rn(a.z * i0.z, a.w * i0.w);
        __half2 h2 = __floats2half2_rn(b.x * i1.x, b.y * i1.y);
        __half2 h3 = __floats2half2_rn(b.z * i1.z, b.w * i1.w);
        uint4 o;
        o.x = *(unsigned*)&h0; o.y = *(unsigned*)&h1;
        o.z = *(unsigned*)&h2; o.w = *(unsigned*)&h3;
        *(uint4*)(g_h + (size_t)row * 64 + seg * 4) = o;
    }

    if (blockIdx.x == 0) {
        __shared__ int any;
        if (threadIdx.x == 0) any = 0;
        __syncthreads();
        int w = e[2 * threadIdx.x + 1];   // odd words zero <=> int64 indices
        if (w != 0) atomicOr(&any, 1);
        __syncthreads();
        if (threadIdx.x == 0) g_is64 = (any == 0) ? 1 : 0;
    }
}

// convert + histogram; packed (r,c) store
__global__ void k_hist(const void* __restrict__ edge) {
    int e = blockIdx.x * blockDim.x + threadIdx.x;
    if (e >= N_EDGES) return;
    int r, c;
    if (g_is64) {
        const long long* p = (const long long*)edge;
        r = (int)p[e];
        c = (int)p[N_EDGES + e];
    } else {
        const int* p = (const int*)edge;
        r = p[e];
        c = p[N_EDGES + e];
    }
    g_rc[e] = make_int2(r, c);
    atomicAdd(&g_cnt[c], 1);
}

// single-pass exclusive scan with decoupled lookback (+ dinv fused)
__global__ void k_scan() {
    __shared__ int s[1024];
    __shared__ int pre;
    int idx = blockIdx.x * 1024 + threadIdx.x;
    int v = (idx < N_NODES) ? g_cnt[idx] : 0;
    if (idx < N_NODES) g_dinv[idx] = rsqrtf((float)(v + 1));
    s[threadIdx.x] = v;
    __syncthreads();
    for (int off = 1; off < 1024; off <<= 1) {
        int t = (threadIdx.x >= off) ? s[threadIdx.x - off] : 0;
        __syncthreads();
        s[threadIdx.x] += t;
        __syncthreads();
    }
    if (threadIdx.x == 1023) {
        g_bsum[blockIdx.x] = s[1023];
        __threadfence();
        atomicExch(&g_bflag[blockIdx.x], 1);
    }
    if (threadIdx.x < 32) {
        int p = 0;
        for (int i = threadIdx.x; i < blockIdx.x; i += 32) {
            while (atomicAdd(&g_bflag[i], 0) == 0) { __nanosleep(100); }
            p += atomicAdd(&g_bsum[i], 0);
        }
#pragma unroll
        for (int o = 16; o; o >>= 1) p += __shfl_xor_sync(0xffffffffu, p, o);
        if (threadIdx.x == 0) pre = p;
    }
    __syncthreads();
    if (idx < N_NODES) g_ptr[idx] = s[threadIdx.x] - v + pre;
    if (idx == 0) g_ptr[N_NODES] = N_EDGES;
}

// bucket fill: cursor = atomicSub on g_cnt (dead after scan); packed edge store
__global__ void k_fill() {
    int e = blockIdx.x * blockDim.x + threadIdx.x;
    if (e >= N_EDGES) return;
    int2 rc = g_rc[e];
    int r = rc.x, c = rc.y;
    int pos = atomicSub(&g_cnt[c], 1) - 1;
    float w = g_dinv[r] * g_dinv[c];
    g_edge[g_ptr[c] + pos] = make_int2(r, __float_as_int(w));
}

// ---------------- mma / math helpers ---------------------------------------
__device__ __forceinline__ void mma_f16(float* d, const unsigned* a, const unsigned* b) {
    asm volatile(
        "mma.sync.aligned.m16n8k16.row.col.f32.f16.f16.f32 "
        "{%0,%1,%2,%3}, {%4,%5,%6,%7}, {%8,%9}, {%0,%1,%2,%3};"
        : "+f"(d[0]), "+f"(d[1]), "+f"(d[2]), "+f"(d[3])
        : "r"(a[0]), "r"(a[1]), "r"(a[2]), "r"(a[3]), "r"(b[0]), "r"(b[1]));
}

__device__ __forceinline__ float gelu_exact(float v) {
    return 0.5f * v * (1.f + erff(v * 0.70710678118654752f));
}

// ---------------- fp16 HMMA GEMM (FINAL=1 fuses head projection) ------------
// A fp16, W = Wh + Wl fp16 split, 2-term m16n8k16. 8 warps 2(M)x4(N).
#define AHS 20     // half2 stride of A smem row
#define WHS 136    // half2 stride of W smem k2-row
#define TSS 68     // half2 stride of fused-final T tile row
#define W2S 20     // half2 stride of lw2 smem k2-row

template <int FINAL>
__global__ void k_gemm_f16(const __half2* __restrict__ A,
                           const __half2* __restrict__ Wh_, const __half2* __restrict__ Wl_,
                           __half2* __restrict__ Y,
                           const float* __restrict__ lb1,
                           const __half2* __restrict__ W2h_, const __half2* __restrict__ W2l_,
                           const float* __restrict__ lb2, float* __restrict__ out) {
    extern __shared__ unsigned char smraw[];
    __half2* As  = (__half2*)smraw;                    // 128*AHS  (10240 B)
    __half2* Whs = (__half2*)(smraw + 10240);          // 16*WHS   (8704 B)
    __half2* Wls = (__half2*)(smraw + 18944);          // 16*WHS   (8704 B)

    int tid = threadIdx.x, lane = tid & 31, wid = tid >> 5;
    int wm = wid >> 2, wn = wid & 3;
    int g = lane >> 2, t4 = lane & 3;
    int row0 = blockIdx.x * 128;

    float acc[4][4][4];
#pragma unroll
    for (int mt = 0; mt < 4; mt++)
#pragma unroll
        for (int nt = 0; nt < 4; nt++)
#pragma unroll
            for (int r = 0; r < 4; r++) acc[mt][nt][r] = 0.f;

    int ar = tid >> 1, part = tid & 1;
    int wkr = tid >> 4, wnq = (tid & 15) * 8;

    for (int kt = 0; kt < 4; kt++) {
        uint4 au0 = make_uint4(0, 0, 0, 0), au1 = au0;
        {
            int gr = row0 + ar;
            if (gr < N_NODES) {
                const uint4* p = (const uint4*)(A + (size_t)gr * 64 + kt * 16 + part * 8);
                au0 = p[0]; au1 = p[1];
            }
        }
        const uint4* ph = (const uint4*)(Wh_ + (size_t)(kt * 16 + wkr) * 128 + wnq);
        const uint4* pl = (const uint4*)(Wl_ + (size_t)(kt * 16 + wkr) * 128 + wnq);
        uint4 wh0 = ph[0], wh1 = ph[1];
        uint4 wl0 = pl[0], wl1 = pl[1];

        __syncthreads();
        {
            uint4* q = (uint4*)(As + ar * AHS + part * 8);
            q[0] = au0; q[1] = au1;
            uint4* qh = (uint4*)(Whs + wkr * WHS + wnq);
            qh[0] = wh0; qh[1] = wh1;
            uint4* ql = (uint4*)(Wls + wkr * WHS + wnq);
            ql[0] = wl0; ql[1] = wl1;
        }
        __syncthreads();

#pragma unroll
        for (int ks = 0; ks < 2; ks++) {
            int kb = ks * 8;
            unsigned a[4][4];
#pragma unroll
            for (int mt = 0; mt < 4; mt++) {
                int rb = wm * 64 + mt * 16;
                a[mt][0] = *(unsigned*)&As[(rb + g) * AHS + kb + t4];
                a[mt][1] = *(unsigned*)&As[(rb + g + 8) * AHS + kb + t4];
                a[mt][2] = *(unsigned*)&As[(rb + g) * AHS + kb + t4 + 4];
                a[mt][3] = *(unsigned*)&As[(rb + g + 8) * AHS + kb + t4 + 4];
            }
            unsigned bh[4][2], bl[4][2];
#pragma unroll
            for (int nt = 0; nt < 4; nt++) {
                int n0 = wn * 32 + nt * 8;
                bh[nt][0] = *(unsigned*)&Whs[(kb + t4) * WHS + n0 + g];
                bh[nt][1] = *(unsigned*)&Whs[(kb + t4 + 4) * WHS + n0 + g];
                bl[nt][0] = *(unsigned*)&Wls[(kb + t4) * WHS + n0 + g];
                bl[nt][1] = *(unsigned*)&Wls[(kb + t4 + 4) * WHS + n0 + g];
            }
#pragma unroll
            for (int mt = 0; mt < 4; mt++)
#pragma unroll
                for (int nt = 0; nt < 4; nt++) {
                    mma_f16(acc[mt][nt], a[mt], bh[nt]);
                    mma_f16(acc[mt][nt], a[mt], bl[nt]);
                }
        }
    }

    if (FINAL == 0) {
#pragma unroll
        for (int mt = 0; mt < 4; mt++) {
            int r1 = row0 + wm * 64 + mt * 16 + g;
            int r2 = r1 + 8;
#pragma unroll
            for (int nt = 0; nt < 4; nt++) {
                int ch = wn * 16 + nt * 4 + t4;
                if (r1 < N_NODES)
                    Y[(size_t)r1 * 64 + ch] = __floats2half2_rn(acc[mt][nt][0], acc[mt][nt][1]);
                if (r2 < N_NODES)
                    Y[(size_t)r2 * 64 + ch] = __floats2half2_rn(acc[mt][nt][2], acc[mt][nt][3]);
            }
        }
    } else {
        // fused head: T = gelu(acc + lb1) in smem, then T @ lw2 (+lb2) -> out
        __half2* Ts   = (__half2*)smraw;                 // 128*TSS  (34816 B)
        __half2* W2hs = (__half2*)(smraw + 34816);       // 64*W2S   (5120 B)
        __half2* W2ls = (__half2*)(smraw + 39936);       // 64*W2S   (5120 B)
        __syncthreads();
        {
            int k2 = tid >> 2, n4 = (tid & 3) * 4;
            *(uint4*)(W2hs + k2 * W2S + n4) = ((const uint4*)W2h_)[tid];
            *(uint4*)(W2ls + k2 * W2S + n4) = ((const uint4*)W2l_)[tid];
        }
#pragma unroll
        for (int mt = 0; mt < 4; mt++) {
            int rl1 = wm * 64 + mt * 16 + g;
            int rl2 = rl1 + 8;
#pragma unroll
            for (int nt = 0; nt < 4; nt++) {
                int c = wn * 32 + nt * 8 + 2 * t4;
                int ch = c >> 1;
                float2 lb = *(const float2*)(lb1 + c);
                Ts[rl1 * TSS + ch] = __floats2half2_rn(gelu_exact(acc[mt][nt][0] + lb.x),
                                                       gelu_exact(acc[mt][nt][1] + lb.y));
                Ts[rl2 * TSS + ch] = __floats2half2_rn(gelu_exact(acc[mt][nt][2] + lb.x),
                                                       gelu_exact(acc[mt][nt][3] + lb.y));
            }
        }
        __syncthreads();
        int rb2 = wid * 16;
        float f2[2][4];
#pragma unroll
        for (int n2 = 0; n2 < 2; n2++)
#pragma unroll
            for (int r = 0; r < 4; r++) f2[n2][r] = 0.f;
#pragma unroll
        for (int kq = 0; kq < 8; kq++) {
            unsigned a[4];
            a[0] = *(unsigned*)&Ts[(rb2 + g) * TSS + kq * 8 + t4];
            a[1] = *(unsigned*)&Ts[(rb2 + g + 8) * TSS + kq * 8 + t4];
            a[2] = *(unsigned*)&Ts[(rb2 + g) * TSS + kq * 8 + t4 + 4];
            a[3] = *(unsigned*)&Ts[(rb2 + g + 8) * TSS + kq * 8 + t4 + 4];
#pragma unroll
            for (int n2 = 0; n2 < 2; n2++) {
                unsigned bh[2], bl[2];
                bh[0] = *(unsigned*)&W2hs[(kq * 8 + t4) * W2S + n2 * 8 + g];
                bh[1] = *(unsigned*)&W2hs[(kq * 8 + t4 + 4) * W2S + n2 * 8 + g];
                bl[0] = *(unsigned*)&W2ls[(kq * 8 + t4) * W2S + n2 * 8 + g];
                bl[1] = *(unsigned*)&W2ls[(kq * 8 + t4 + 4) * W2S + n2 * 8 + g];
                mma_f16(f2[n2], a, bh);
                mma_f16(f2[n2], a, bl);
            }
        }
        int r1 = row0 + rb2 + g, r2 = r1 + 8;
#pragma unroll
        for (int n2 = 0; n2 < 2; n2++) {
            int c = n2 * 8 + 2 * t4;
            float2 lb = *(const float2*)(lb2 + c);
            if (r1 < N_NODES)
                *(float2*)(out + (size_t)r1 * CDIM + c) = make_float2(f2[n2][0] + lb.x, f2[n2][1] + lb.y);
            if (r2 < N_NODES)
                *(float2*)(out + (size_t)r2 * CDIM + c) = make_float2(f2[n2][2] + lb.x, f2[n2][3] + lb.y);
        }
    }
}

// ---------------- aggregation (shfl-free, 16 lanes/node, packed edges) ------
__device__ __forceinline__ void fma8(float* acc, uint4 u, float w) {
    float2 a = __half22float2(*(__half2*)&u.x);
    float2 b = __half22float2(*(__half2*)&u.y);
    float2 c = __half22float2(*(__half2*)&u.z);
    float2 d = __half22float2(*(__half2*)&u.w);
    acc[0] += w * a.x; acc[1] += w * a.y;
    acc[2] += w * b.x; acc[3] += w * b.y;
    acc[4] += w * c.x; acc[5] += w * c.y;
    acc[6] += w * d.x; acc[7] += w * d.y;
}

__global__ void k_agg(const __half2* __restrict__ Y, const float* __restrict__ b,
                      __half2* __restrict__ H) {
    int tid  = threadIdx.x;
    int warp = tid >> 5;
    int lane = tid & 31;
    int sub  = lane & 15;
    int c = blockIdx.x * 16 + warp * 2 + (lane >> 4);

    float dc = g_dinv[c];
    float sw = dc * dc;
    float acc[8] = {0, 0, 0, 0, 0, 0, 0, 0};
    fma8(acc, *(const uint4*)(Y + (size_t)c * 64 + sub * 4), sw);

    int beg = g_ptr[c], end = g_ptr[c + 1];
    int i = beg;
    for (; i + 4 <= end; i += 4) {
        int2 e0 = g_edge[i],     e1 = g_edge[i + 1];
        int2 e2 = g_edge[i + 2], e3 = g_edge[i + 3];
        uint4 u0 = *(const uint4*)(Y + (size_t)e0.x * 64 + sub * 4);
        uint4 u1 = *(const uint4*)(Y + (size_t)e1.x * 64 + sub * 4);
        uint4 u2 = *(const uint4*)(Y + (size_t)e2.x * 64 + sub * 4);
        uint4 u3 = *(const uint4*)(Y + (size_t)e3.x * 64 + sub * 4);
        fma8(acc, u0, __int_as_float(e0.y));
        fma8(acc, u1, __int_as_float(e1.y));
        fma8(acc, u2, __int_as_float(e2.y));
        fma8(acc, u3, __int_as_float(e3.y));
    }
    for (; i < end; i++) {
        int2 e = g_edge[i];
        fma8(acc, *(const uint4*)(Y + (size_t)e.x * 64 + sub * 4), __int_as_float(e.y));
    }

    const float4 b0 = *(const float4*)(b + sub * 8);
    const float4 b1 = *(const float4*)(b + sub * 8 + 4);
    uint4 o;
    __half2 h0 = __floats2half2_rn(gelu_exact(acc[0] + b0.x), gelu_exact(acc[1] + b0.y));
    __half2 h1 = __floats2half2_rn(gelu_exact(acc[2] + b0.z), gelu_exact(acc[3] + b0.w));
    __half2 h2 = __floats2half2_rn(gelu_exact(acc[4] + b1.x), gelu_exact(acc[5] + b1.y));
    __half2 h3 = __floats2half2_rn(gelu_exact(acc[6] + b1.z), gelu_exact(acc[7] + b1.w));
    o.x = *(unsigned*)&h0; o.y = *(unsigned*)&h1; o.z = *(unsigned*)&h2; o.w = *(unsigned*)&h3;
    *(uint4*)(H + (size_t)c * 64 + sub * 4) = o;
}

// ---------------- launch ---------------------------------------------------
extern "C" void kernel_launch(void* const* d_in, const int* in_sizes, int n_in,
                              void* d_out, int out_size) {
    const float* x    = (const float*)d_in[0];
    const void*  edge = d_in[1];
    const float* imp  = (const float*)d_in[2];
    const float* W1   = (const float*)d_in[3];
    const float* b1   = (const float*)d_in[4];
    const float* W2   = (const float*)d_in[5];
    const float* b2   = (const float*)d_in[6];
    const float* W3   = (const float*)d_in[7];
    const float* b3   = (const float*)d_in[8];
    const float* lw1  = (const float*)d_in[9];
    const float* lb1  = (const float*)d_in[10];
    const float* lw2  = (const float*)d_in[11];
    const float* lb2  = (const float*)d_in[12];
    float* out = (float*)d_out;

    const int EB = (N_EDGES + 255) / 256;      // 3125
    const int SB = (N_NODES + 1023) / 1024;    // 49
    const int GB = (N_NODES + 127) / 128;      // 391
    const int AB = N_NODES / 16;               // 3125

    __half2* y; cudaGetSymbolAddress((void**)&y, g_y);
    __half2* h; cudaGetSymbolAddress((void**)&h, g_h);
    __half2* wh; cudaGetSymbolAddress((void**)&wh, g_Whf);
    __half2* wl; cudaGetSymbolAddress((void**)&wl, g_Wlf);

    const int SM_MAIN = 27648;   // As + Wh + Wl
    const int SM_FIN  = 45056;   // Ts + W2h + W2l overlay

    // --- init (counters, weight packs, x->fp16, dtype) + CSR build ---
    k_init<<<256, 256>>>((const int*)edge, W1, W2, W3, lw1, lw2, x, imp);
    k_hist<<<EB, 256>>>(edge);
    k_scan<<<SB, 1024>>>();
    k_fill<<<EB, 256>>>();

    // --- layer 1 (fp16 A = x*imp, 2-term) ---
    k_gemm_f16<0><<<GB, 256, SM_MAIN>>>(h, wh, wl, y, nullptr, nullptr, nullptr, nullptr, nullptr);
    k_agg<<<AB, 256>>>(y, b1, h);
    // --- layer 2 ---
    k_gemm_f16<0><<<GB, 256, SM_MAIN>>>(h, wh + 8192, wl + 8192, y, nullptr, nullptr, nullptr, nullptr, nullptr);
    k_agg<<<AB, 256>>>(y, b2, h);
    // --- layer 3 ---
    k_gemm_f16<0><<<GB, 256, SM_MAIN>>>(h, wh + 16384, wl + 16384, y, nullptr, nullptr, nullptr, nullptr, nullptr);
    k_agg<<<AB, 256>>>(y, b3, h);
    // --- head (fused: gelu(h@lw1+lb1) @ lw2 + lb2 -> out) ---
    k_gemm_f16<1><<<GB, 256, SM_FIN>>>(h, wh + 24576, wl + 24576, nullptr, lb1,
                                       wh + 32768, wl + 32768, lb2, out);
}